// round 12
// baseline (speedup 1.0000x reference)
#include <cuda_runtime.h>
#include <math.h>

#define LDA 132
#define WCH 4096
#define NT 256
#define NTM 512

__device__ float g_sq[(size_t)20000 * 128];

// fragment-packed tf32 weights
#define W_EW  0
#define W_Q   16384
#define W_K   32768
#define W_V   49152
#define W_QS  65536
#define W_AFC 81920
#define W_F1  98304
#define W_F2  163840
#define W_TOT 229376
__device__ float g_wbuf[W_TOT];

__device__ __forceinline__ float gelu_exact(float x) {
    return 0.5f * x * (1.0f + erff(x * 0.7071067811865475f));
}
__device__ __forceinline__ float to_tf32(float x) {
    unsigned u;
    asm("cvt.rna.tf32.f32 %0, %1;" : "=r"(u) : "f"(x));
    return __uint_as_float(u);
}
__device__ __forceinline__ void mma_tf32(float d[4], const float a[4], const float b[2]) {
    asm volatile(
        "mma.sync.aligned.m16n8k8.row.col.f32.tf32.tf32.f32 "
        "{%0,%1,%2,%3}, {%4,%5,%6,%7}, {%8,%9}, {%0,%1,%2,%3};"
        : "+f"(d[0]), "+f"(d[1]), "+f"(d[2]), "+f"(d[3])
        : "r"(__float_as_uint(a[0])), "r"(__float_as_uint(a[1])),
          "r"(__float_as_uint(a[2])), "r"(__float_as_uint(a[3])),
          "r"(__float_as_uint(b[0])), "r"(__float_as_uint(b[1])));
}

#define ACC_ZERO2(acc) do { _Pragma("unroll") for (int _m=0;_m<2;_m++) _Pragma("unroll") for (int _n=0;_n<4;_n++) { acc[_m][_n][0]=0.f;acc[_m][_n][1]=0.f;acc[_m][_n][2]=0.f;acc[_m][_n][3]=0.f; } } while(0)

__device__ __forceinline__ void cpa16(float* dst, const float* src) {
    unsigned u = (unsigned)__cvta_generic_to_shared(dst);
    asm volatile("cp.async.cg.shared.global [%0], [%1], 16;\n" :: "r"(u), "l"(src));
}
#define CP_COMMIT() asm volatile("cp.async.commit_group;\n")
#define CP_WAIT(n)  asm volatile("cp.async.wait_group %0;\n" :: "n"(n))

// ---------------- 256-thread, M=64 GEMM (double-buffered) for k_sq ----------
__device__ __forceinline__ void stageWp(float* dst, const float* __restrict__ W,
                                        int kc, int tid) {
#pragma unroll
    for (int j = 0; j < 4; j++) {
        int idx = (tid + j * NT) << 2;
        cpa16(dst + idx, W + kc * WCH + idx);
    }
}

__device__ __forceinline__ void gemm128p(float acc[2][4][4], const float* sAct,
                                         const float* __restrict__ Wg,
                                         float* sWbuf, int tid) {
    const int lane = tid & 31, w = tid >> 5;
    const int mg = w & 1, ng = w >> 1;
    const int qr = lane >> 2, qc = lane & 3;
    stageWp(sWbuf, Wg, 0, tid);
    CP_COMMIT();
#pragma unroll
    for (int kc = 0; kc < 4; kc++) {
        const float* sw = sWbuf + (kc & 1) * WCH;
        if (kc < 3) {
            stageWp(sWbuf + ((kc + 1) & 1) * WCH, Wg, kc + 1, tid);
            CP_COMMIT();
            CP_WAIT(1);
        } else {
            CP_WAIT(0);
        }
        __syncthreads();
#pragma unroll
        for (int ks2 = 0; ks2 < 2; ks2++) {
            float4 bf4[4];
#pragma unroll
            for (int nt = 0; nt < 4; nt++) {
                int n = (ng * 4 + nt) * 8 + qr;
                bf4[nt] = *(const float4*)(sw + ks2 * 2048 + n * 16 + qc * 4);
            }
#pragma unroll
            for (int sub = 0; sub < 2; sub++) {
                const int k0 = kc * 32 + ks2 * 16 + sub * 8;
                float af[2][4];
#pragma unroll
                for (int mt = 0; mt < 2; mt++) {
                    const float* ap = sAct + ((mg * 2 + mt) * 16 + qr) * LDA + k0 + qc;
                    af[mt][0] = ap[0];
                    af[mt][1] = ap[8 * LDA];
                    af[mt][2] = ap[4];
                    af[mt][3] = ap[8 * LDA + 4];
                }
#pragma unroll
                for (int nt = 0; nt < 4; nt++) {
                    float b2[2];
                    b2[0] = sub ? bf4[nt].z : bf4[nt].x;
                    b2[1] = sub ? bf4[nt].w : bf4[nt].y;
                    mma_tf32(acc[0][nt], af[0], b2);
                    mma_tf32(acc[1][nt], af[1], b2);
                }
            }
        }
        __syncthreads();
    }
}

// ---------------- 512-thread, M=128 GEMM (single-buffered W) ----------------
__device__ __forceinline__ void stageW512(float* dst, const float* __restrict__ W,
                                          int kc, int tid) {
#pragma unroll
    for (int j = 0; j < 2; j++) {
        int idx = (tid + j * NTM) << 2;
        cpa16(dst + idx, W + kc * WCH + idx);
    }
}

__device__ __forceinline__ void gemmM128(float acc[2][4][4], const float* sAct,
                                         const float* __restrict__ Wg,
                                         float* sWbuf, int tid) {
    const int lane = tid & 31, w = tid >> 5;
    const int mg = w >> 2, ng = w & 3;
    const int qr = lane >> 2, qc = lane & 3;
#pragma unroll
    for (int kc = 0; kc < 4; kc++) {
        stageW512(sWbuf, Wg, kc, tid);
        CP_COMMIT();
        CP_WAIT(0);
        __syncthreads();
#pragma unroll
        for (int ks2 = 0; ks2 < 2; ks2++) {
            float4 bf4[4];
#pragma unroll
            for (int nt = 0; nt < 4; nt++) {
                int n = (ng * 4 + nt) * 8 + qr;
                bf4[nt] = *(const float4*)(sWbuf + ks2 * 2048 + n * 16 + qc * 4);
            }
#pragma unroll
            for (int sub = 0; sub < 2; sub++) {
                const int k0 = kc * 32 + ks2 * 16 + sub * 8;
                float af[2][4];
#pragma unroll
                for (int mt = 0; mt < 2; mt++) {
                    const float* ap = sAct + (mg * 32 + mt * 16 + qr) * LDA + k0 + qc;
                    af[mt][0] = ap[0];
                    af[mt][1] = ap[8 * LDA];
                    af[mt][2] = ap[4];
                    af[mt][3] = ap[8 * LDA + 4];
                }
#pragma unroll
                for (int nt = 0; nt < 4; nt++) {
                    float b2[2];
                    b2[0] = sub ? bf4[nt].z : bf4[nt].x;
                    b2[1] = sub ? bf4[nt].w : bf4[nt].y;
                    mma_tf32(acc[0][nt], af[0], b2);
                    mma_tf32(acc[1][nt], af[1], b2);
                }
            }
        }
        __syncthreads();
    }
}

// store acc to smem (128 rows, stride LDA)
__device__ __forceinline__ void storeS(float* dst, float acc[2][4][4], int tid, bool rnd) {
    const int lane = tid & 31, w = tid >> 5;
    const int mg = w >> 2, ng = w & 3;
    const int qr = lane >> 2, qc = lane & 3;
#pragma unroll
    for (int mt = 0; mt < 2; mt++)
#pragma unroll
        for (int hh = 0; hh < 2; hh++) {
            int r = mg * 32 + mt * 16 + qr + hh * 8;
#pragma unroll
            for (int nt = 0; nt < 4; nt++) {
                int c = (ng * 4 + nt) * 8 + qc * 2;
                float v0 = acc[mt][nt][hh * 2], v1 = acc[mt][nt][hh * 2 + 1];
                if (rnd) { v0 = to_tf32(v0); v1 = to_tf32(v1); }
                dst[r * LDA + c] = v0;
                dst[r * LDA + c + 1] = v1;
            }
        }
}

// ------------------- kernel 0: pack weights to fragment order (tf32) --------
__global__ void k_prep(const float* __restrict__ e_w, const float* __restrict__ wq,
                       const float* __restrict__ wk, const float* __restrict__ wv,
                       const float* __restrict__ wq_src, const float* __restrict__ afc_w,
                       const float* __restrict__ f_w1, const float* __restrict__ f_w2)
{
    int i = blockIdx.x * 256 + threadIdx.x;
    if (i >= W_TOT) return;
    const float* src; int rel; int ldw = 128; int kbase = 0; int nbase = 0;
    if      (i < W_Q)   { src = e_w;    rel = i - W_EW; }
    else if (i < W_K)   { src = wq;     rel = i - W_Q; }
    else if (i < W_V)   { src = wk;     rel = i - W_K; }
    else if (i < W_QS)  { src = wv;     rel = i - W_V; }
    else if (i < W_AFC) { src = wq_src; rel = i - W_QS; }
    else if (i < W_F1)  { src = afc_w;  rel = i - W_AFC; }
    else if (i < W_F2)  { src = f_w1;   rel = i - W_F1;
                          int c = rel / 16384; rel -= c * 16384; ldw = 512; nbase = c * 128; }
    else                { src = f_w2;   rel = i - W_F2;
                          int c = rel / 16384; rel -= c * 16384; kbase = c * 128; }
    int kc = rel >> 12;
    int within = rel & 4095;
    int ks2 = within >> 11;
    int remn = within & 2047;
    int n = remn >> 4;
    int rem2 = remn & 15;
    int qc = rem2 >> 2;
    int e = rem2 & 3;
    int k = kc * 32 + ks2 * 16 + qc + (e & 1) * 4 + (e >> 1) * 8;
    g_wbuf[i] = to_tf32(src[(size_t)(kbase + k) * ldw + nbase + n]);
}

// ------------------- kernel 1: self_q precompute -> g_sq -------------------
__global__ __launch_bounds__(NT, 2)
void k_sq(const float* __restrict__ nh, const float* __restrict__ t,
          const float* __restrict__ t_now, const float* __restrict__ ef,
          const float* __restrict__ bfreq, const float* __restrict__ phase,
          const float* __restrict__ e_b, int Ntot)
{
    extern __shared__ float sm[];
    float* sA = sm;
    float* sZ = sm + 64 * LDA;
    float* sW = sZ + 64 * LDA;
    const int tid = threadIdx.x;
    const int n0 = blockIdx.x * 64;
    const int rv = min(64, Ntot - n0);

    // stage ef rows (n*20+19), tf32
#pragma unroll
    for (int j = 0; j < 8; j++) {
        int idx = tid + j * NT;
        int r = idx >> 5;
        int c4 = (idx & 31) << 2;
        float4 v = make_float4(0.f, 0.f, 0.f, 0.f);
        if (r < rv) v = *(const float4*)(ef + ((size_t)(n0 + r) * 20 + 19) * 128 + c4);
        float4 o;
        o.x = to_tf32(v.x); o.y = to_tf32(v.y); o.z = to_tf32(v.z); o.w = to_tf32(v.w);
        *(float4*)(sA + r * LDA + c4) = o;
    }
    __syncthreads();

    float acc[2][4][4];
    ACC_ZERO2(acc);
    gemm128p(acc, sA, g_wbuf + W_EW, sW, tid);

    const float tn = t_now[0];
    const int lane = tid & 31, w = tid >> 5;
    const int mg = w & 1, ng = w >> 1;
    const int qr = lane >> 2, qc = lane & 3;
#pragma unroll
    for (int mt = 0; mt < 2; mt++)
#pragma unroll
        for (int hh = 0; hh < 2; hh++) {
            int lr = (mg * 2 + mt) * 16 + qr + hh * 8;
            bool ok = (lr < rv);
            long grow = (long)(n0 + lr) * 20 + 19;
            float tv = ok ? t[grow] : 0.f;
#pragma unroll
            for (int nt = 0; nt < 4; nt++)
#pragma unroll
                for (int p = 0; p < 2; p++) {
                    int cc = (ng * 4 + nt) * 8 + qc * 2 + p;
                    float zv = 0.f;
                    if (ok) {
                        float g = gelu_exact(acc[mt][nt][hh * 2 + p] + e_b[cc]);
                        float te = cosf((tn - tv) * bfreq[cc] + phase[cc]);
                        zv = to_tf32(nh[(size_t)grow * 128 + cc] + g + te);
                    }
                    sZ[lr * LDA + cc] = zv;
                }
        }
    __syncthreads();

    ACC_ZERO2(acc);
    gemm128p(acc, sZ, g_wbuf + W_QS, sW, tid);
#pragma unroll
    for (int mt = 0; mt < 2; mt++)
#pragma unroll
        for (int hh = 0; hh < 2; hh++) {
            int lr = (mg * 2 + mt) * 16 + qr + hh * 8;
            if (lr < rv)
#pragma unroll
                for (int nt = 0; nt < 4; nt++) {
                    int c = (ng * 4 + nt) * 8 + qc * 2;
                    float2 a;
                    a.x = to_tf32(acc[mt][nt][hh * 2]);
                    a.y = to_tf32(acc[mt][nt][hh * 2 + 1]);
                    *(float2*)(g_sq + (size_t)(n0 + lr) * 128 + c) = a;
                }
        }
}

// ------------------- kernel 2: MEGA (6 nodes, everything fused) -------------
__global__ __launch_bounds__(NTM, 1)
void k_mega(const float* __restrict__ nh, const float* __restrict__ t,
            const float* __restrict__ t_now, const float* __restrict__ ef,
            const float* __restrict__ bfreq, const float* __restrict__ phase,
            const float* __restrict__ e_b,
            const float* __restrict__ afc_b, const float* __restrict__ aln_g,
            const float* __restrict__ aln_b,
            const float* __restrict__ f_b1, const float* __restrict__ f_b2,
            const float* __restrict__ fln_g, const float* __restrict__ fln_b,
            const float* __restrict__ f2n_w, const float* __restrict__ f2n_b,
            const float* __restrict__ oln_g, const float* __restrict__ oln_b,
            float* __restrict__ out, int Ntot)
{
    extern __shared__ float sm[];
    float* sA  = sm;                       // 128*LDA : ef -> K -> O -> H -> y2
    float* sB  = sm + 128 * LDA;           // z -> x(pre-LN)
    float* sC  = sm + 2 * 128 * LDA;       // Q -> V -> x(post-LN)
    float* sW  = sm + 3 * 128 * LDA;       // WCH
    float* scr = sW + WCH;                 // 2048
    const int tid = threadIdx.x;
    const int nb0 = blockIdx.x * 6;
    const int nodes_here = min(6, Ntot - nb0);
    const int rows = nodes_here * 20;
    const long grow0 = (long)nb0 * 20;

    // ---- stage ef -> sA (tf32), pad rows zero ----
#pragma unroll
    for (int j = 0; j < 8; j++) {
        int idx = tid + j * NTM;
        int r = idx >> 5;
        int c4 = (idx & 31) << 2;
        float4 v = make_float4(0.f, 0.f, 0.f, 0.f);
        if (r < rows) v = *(const float4*)(ef + (size_t)(grow0 + r) * 128 + c4);
        float4 o;
        o.x = to_tf32(v.x); o.y = to_tf32(v.y); o.z = to_tf32(v.z); o.w = to_tf32(v.w);
        *(float4*)(sA + r * LDA + c4) = o;
    }
    __syncthreads();

    const int lane = tid & 31, w = tid >> 5;
    const int mg = w >> 2, ng = w & 3;
    const int qr = lane >> 2, qc = lane & 3;

    float acc[2][4][4];

    // ---- edge GEMM + z epilogue -> sB ----
    ACC_ZERO2(acc);
    gemmM128(acc, sA, g_wbuf + W_EW, sW, tid);
    const float tn = t_now[0];
#pragma unroll
    for (int mt = 0; mt < 2; mt++)
#pragma unroll
        for (int hh = 0; hh < 2; hh++) {
            int lr = mg * 32 + mt * 16 + qr + hh * 8;
            bool ok = (lr < rows);
            float tv = ok ? t[grow0 + lr] : 0.f;
#pragma unroll
            for (int nt = 0; nt < 4; nt++)
#pragma unroll
                for (int p = 0; p < 2; p++) {
                    int cc = (ng * 4 + nt) * 8 + qc * 2 + p;
                    float zv = 0.f;
                    if (ok) {
                        float g = gelu_exact(acc[mt][nt][hh * 2 + p] + e_b[cc]);
                        float te = cosf((tn - tv) * bfreq[cc] + phase[cc]);
                        zv = to_tf32(nh[(size_t)(grow0 + lr) * 128 + cc] + g + te);
                    }
                    sB[lr * LDA + cc] = zv;
                }
        }
    // (first sync inside next gemm orders sB writes before reads)

    // ---- Q -> sC, K -> sA ----
    ACC_ZERO2(acc); gemmM128(acc, sB, g_wbuf + W_Q, sW, tid); storeS(sC, acc, tid, true);
    ACC_ZERO2(acc); gemmM128(acc, sB, g_wbuf + W_K, sW, tid); storeS(sA, acc, tid, true);

    // load self_q -> scr[0..768)
    for (int i = tid; i < nodes_here * 128; i += NTM)
        scr[i] = g_sq[(size_t)(nb0 + (i >> 7)) * 128 + (i & 127)];
    __syncthreads();
    // splice into Q and K rows 19
    for (int i = tid; i < nodes_here * 128; i += NTM) {
        int node = i >> 7, d = i & 127;
        int r = node * 20 + 19;
        sC[r * LDA + d] = scr[i];
        sA[r * LDA + d] = scr[i];
    }
    __syncthreads();

    // ---- attention phase 1: scores + softmax (p stays in regs) ----
    const int anode = tid / 80, ah = (tid / 20) % 4, aqi = tid % 20;
    const bool act = tid < nodes_here * 80;
    float p[20];
    if (act) {
        float qreg[32];
        const float* qp = sC + (anode * 20 + aqi) * LDA + ah * 32;
#pragma unroll
        for (int j = 0; j < 8; j++) {
            float4 v = *(const float4*)(qp + j * 4);
            qreg[4*j] = v.x; qreg[4*j+1] = v.y; qreg[4*j+2] = v.z; qreg[4*j+3] = v.w;
        }
#pragma unroll
        for (int ki = 0; ki < 20; ki++) {
            const float* kp = sA + (anode * 20 + ki) * LDA + ah * 32;
            float s = 0.f;
#pragma unroll
            for (int j = 0; j < 8; j++) {
                float4 kv = *(const float4*)(kp + j * 4);
                s += qreg[4*j] * kv.x + qreg[4*j+1] * kv.y + qreg[4*j+2] * kv.z + qreg[4*j+3] * kv.w;
            }
            p[ki] = s * 0.17677669529663687f;
        }
        float m = p[0];
#pragma unroll
        for (int ki = 1; ki < 20; ki++) m = fmaxf(m, p[ki]);
        float ssum = 0.f;
#pragma unroll
        for (int ki = 0; ki < 20; ki++) { p[ki] = expf(p[ki] - m); ssum += p[ki]; }
        float inv = 1.f / ssum;
#pragma unroll
        for (int ki = 0; ki < 20; ki++) p[ki] *= inv;
    }
    __syncthreads();   // Q/K reads done; sC reusable

    // ---- V -> sC (p survives in registers) ----
    ACC_ZERO2(acc); gemmM128(acc, sB, g_wbuf + W_V, sW, tid); storeS(sC, acc, tid, true);
    __syncthreads();
    for (int i = tid; i < nodes_here * 128; i += NTM) {
        int node = i >> 7, d = i & 127;
        sC[(node * 20 + 19) * LDA + d] = scr[i];
    }
    __syncthreads();

    // ---- attention phase 2: O = P @ V -> sA (pad rows of sA are 0 from K) ----
    if (act) {
        float oacc[32];
#pragma unroll
        for (int j = 0; j < 32; j++) oacc[j] = 0.f;
#pragma unroll
        for (int ki = 0; ki < 20; ki++) {
            float pw = p[ki];
            const float* vp = sC + (anode * 20 + ki) * LDA + ah * 32;
#pragma unroll
            for (int j = 0; j < 8; j++) {
                float4 vv = *(const float4*)(vp + j * 4);
                oacc[4*j]   += pw * vv.x; oacc[4*j+1] += pw * vv.y;
                oacc[4*j+2] += pw * vv.z; oacc[4*j+3] += pw * vv.w;
            }
        }
        float* op = sA + (anode * 20 + aqi) * LDA + ah * 32;
#pragma unroll
        for (int j = 0; j < 8; j++) {
            float4 v;
            v.x = to_tf32(oacc[4*j]);   v.y = to_tf32(oacc[4*j+1]);
            v.z = to_tf32(oacc[4*j+2]); v.w = to_tf32(oacc[4*j+3]);
            *(float4*)(op + j * 4) = v;
        }
    }
    __syncthreads();

    // ---- attn_fc GEMM + bias + z residual -> sB (in place) ----
    ACC_ZERO2(acc);
    gemmM128(acc, sA, g_wbuf + W_AFC, sW, tid);
#pragma unroll
    for (int mt = 0; mt < 2; mt++)
#pragma unroll
        for (int hh = 0; hh < 2; hh++) {
            int lr = mg * 32 + mt * 16 + qr + hh * 8;
            if (lr < rows)
#pragma unroll
                for (int nt = 0; nt < 4; nt++)
#pragma unroll
                    for (int p2 = 0; p2 < 2; p2++) {
                        int cc = (ng * 4 + nt) * 8 + qc * 2 + p2;
                        sB[lr * LDA + cc] = acc[mt][nt][hh * 2 + p2] + afc_b[cc] + sB[lr * LDA + cc];
                    }
        }
    __syncthreads();

    // ---- attn LN: sB -> sC (tf32). sC pad rows stay 0 (from V). ----
    float* stats = scr + 768;
    if (tid < rows) {
        float m = 0.f;
#pragma unroll 8
        for (int dd = 0; dd < 128; dd++) m += sB[tid * LDA + ((dd + tid) & 127)];
        m *= (1.0f / 128.0f);
        float v = 0.f;
#pragma unroll 8
        for (int dd = 0; dd < 128; dd++) { float x = sB[tid * LDA + ((dd + tid) & 127)] - m; v += x * x; }
        v *= (1.0f / 128.0f);
        stats[tid] = m;
        stats[128 + tid] = rsqrtf(v + 1e-5f);
    }
    __syncthreads();
    for (int i = tid; i < rows * 128; i += NTM) {
        int r = i >> 7, d = i & 127;
        float y = (sB[r * LDA + d] - stats[r]) * stats[128 + r] * aln_g[d] + aln_b[d];
        sC[r * LDA + d] = to_tf32(y);
    }
    __syncthreads();

    // ---- FFN: 4 column chunks, x2 accumulated in registers ----
    float x2[2][4][4];
    ACC_ZERO2(x2);
    for (int c = 0; c < 4; c++) {
        ACC_ZERO2(acc);
        gemmM128(acc, sC, g_wbuf + W_F1 + c * 16384, sW, tid);
#pragma unroll
        for (int mt = 0; mt < 2; mt++)
#pragma unroll
            for (int hh = 0; hh < 2; hh++) {
                int r = mg * 32 + mt * 16 + qr + hh * 8;
#pragma unroll
                for (int nt = 0; nt < 4; nt++) {
                    int col = (ng * 4 + nt) * 8 + qc * 2;
                    float b0 = f_b1[c * 128 + col], b1 = f_b1[c * 128 + col + 1];
                    sA[r * LDA + col]     = to_tf32(fmaxf(acc[mt][nt][hh * 2] + b0, 0.f));
                    sA[r * LDA + col + 1] = to_tf32(fmaxf(acc[mt][nt][hh * 2 + 1] + b1, 0.f));
                }
            }
        gemmM128(x2, sA, g_wbuf + W_F2 + c * 16384, sW, tid);
    }
    // x2 + b2 + x(sC) -> sA
#pragma unroll
    for (int mt = 0; mt < 2; mt++)
#pragma unroll
        for (int hh = 0; hh < 2; hh++) {
            int r = mg * 32 + mt * 16 + qr + hh * 8;
#pragma unroll
            for (int nt = 0; nt < 4; nt++) {
                int col = (ng * 4 + nt) * 8 + qc * 2;
                float b0 = f_b2[col], b1 = f_b2[col + 1];
                sA[r * LDA + col]     = x2[mt][nt][hh * 2]     + b0 + sC[r * LDA + col];
                sA[r * LDA + col + 1] = x2[mt][nt][hh * 2 + 1] + b1 + sC[r * LDA + col + 1];
            }
        }
    __syncthreads();

    // ---- FFN LN: sA in place ----
    if (tid < rows) {
        float m = 0.f;
#pragma unroll 8
        for (int dd = 0; dd < 128; dd++) m += sA[tid * LDA + ((dd + tid) & 127)];
        m *= (1.0f / 128.0f);
        float v = 0.f;
#pragma unroll 8
        for (int dd = 0; dd < 128; dd++) { float x = sA[tid * LDA + ((dd + tid) & 127)] - m; v += x * x; }
        v *= (1.0f / 128.0f);
        stats[tid] = m;
        stats[128 + tid] = rsqrtf(v + 1e-5f);
    }
    __syncthreads();
    for (int i = tid; i < rows * 128; i += NTM) {
        int r = i >> 7, d = i & 127;
        sA[r * LDA + d] = (sA[r * LDA + d] - stats[r]) * stats[128 + r] * fln_g[d] + fln_b[d];
    }
    __syncthreads();

    // ---- fuse: neighborhood mean, fea2node, out LN ----
    float* sNe = scr;          // overwrite sq (dead)
    for (int i = tid; i < nodes_here * 128; i += NTM) {
        int node = i >> 7, d = i & 127;
        float s = 0.f;
#pragma unroll
        for (int k = 0; k < 19; k++) s += sA[(node * 20 + k) * LDA + d];
        sNe[i] = s * (1.0f / 19.0f);
    }
    __syncthreads();
    float* sY = scr + 768;     // overwrite stats (dead)
    for (int idx = tid; idx < nodes_here * 128; idx += NTM) {
        int node = idx >> 7, d = idx & 127;
        const float* selfr = sA + (node * 20 + 19) * LDA;
        const float* ne = sNe + node * 128;
        float a = 0.f;
#pragma unroll 4
        for (int e = 0; e < 128; e++) a += selfr[e] * f2n_w[e * 128 + d];
#pragma unroll 4
        for (int e = 0; e < 128; e++) a += ne[e] * f2n_w[(128 + e) * 128 + d];
        float y = gelu_exact(a + f2n_b[d])
                + nh[((size_t)(nb0 + node) * 20 + 19) * 128 + d];
        sY[idx] = y;
    }
    __syncthreads();
    if (tid < nodes_here) {
        float m = 0.f;
        for (int d = 0; d < 128; d++) m += sY[tid * 128 + d];
        m *= (1.0f / 128.0f);
        float v = 0.f;
        for (int d = 0; d < 128; d++) { float x = sY[tid * 128 + d] - m; v += x * x; }
        v *= (1.0f / 128.0f);
        scr[1536 + tid] = m;
        scr[1552 + tid] = rsqrtf(v + 1e-5f);
    }
    __syncthreads();
    for (int idx = tid; idx < nodes_here * 128; idx += NTM) {
        int node = idx >> 7, d = idx & 127;
        float y = (sY[idx] - scr[1536 + node]) * scr[1552 + node];
        out[(size_t)(nb0 + node) * 128 + d] = y * oln_g[d] + oln_b[d];
    }
}

// ------------------- launch -------------------
#define SM_SQ   ((2 * 64 * LDA + 2 * WCH) * 4)
#define SM_MEGA ((3 * 128 * LDA + WCH + 2048) * 4)

extern "C" void kernel_launch(void* const* d_in, const int* in_sizes, int n_in,
                              void* d_out, int out_size) {
    (void)n_in; (void)out_size;
    const float* nh      = (const float*)d_in[0];
    const float* t       = (const float*)d_in[1];
    const float* t_now   = (const float*)d_in[2];
    const float* ef      = (const float*)d_in[3];
    const float* bfreq   = (const float*)d_in[4];
    const float* phase   = (const float*)d_in[5];
    const float* e_w     = (const float*)d_in[6];
    const float* e_b     = (const float*)d_in[7];
    const float* wq      = (const float*)d_in[8];
    const float* wk      = (const float*)d_in[9];
    const float* wv      = (const float*)d_in[10];
    const float* wq_src  = (const float*)d_in[11];
    const float* afc_w   = (const float*)d_in[12];
    const float* afc_b   = (const float*)d_in[13];
    const float* aln_g   = (const float*)d_in[14];
    const float* aln_b   = (const float*)d_in[15];
    const float* f_w1    = (const float*)d_in[16];
    const float* f_b1    = (const float*)d_in[17];
    const float* f_w2    = (const float*)d_in[18];
    const float* f_b2    = (const float*)d_in[19];
    const float* fln_g   = (const float*)d_in[20];
    const float* fln_b   = (const float*)d_in[21];
    const float* f2n_w   = (const float*)d_in[22];
    const float* f2n_b   = (const float*)d_in[23];
    const float* oln_g   = (const float*)d_in[24];
    const float* oln_b   = (const float*)d_in[25];
    float* out = (float*)d_out;

    const int N = in_sizes[0] / 2560;

    cudaFuncSetAttribute(k_sq,   cudaFuncAttributeMaxDynamicSharedMemorySize, SM_SQ);
    cudaFuncSetAttribute(k_mega, cudaFuncAttributeMaxDynamicSharedMemorySize, SM_MEGA);

    k_prep<<<(W_TOT + 255) / 256, 256>>>(e_w, wq, wk, wv, wq_src, afc_w, f_w1, f_w2);
    k_sq<<<(N + 63) / 64, NT, SM_SQ>>>(nh, t, t_now, ef, bfreq, phase, e_b, N);
    k_mega<<<(N + 5) / 6, NTM, SM_MEGA>>>(nh, t, t_now, ef, bfreq, phase, e_b,
                                          afc_b, aln_g, aln_b,
                                          f_b1, f_b2, fln_g, fln_b,
                                          f2n_w, f2n_b, oln_g, oln_b, out, N);
}

// round 13
// speedup vs baseline: 1.0659x; 1.0659x over previous
#include <cuda_runtime.h>
#include <math.h>

#define LDA 132
#define NT 256
#define WCH 4096
#define MAXROWS (20000*20)

__device__ float g_z[(size_t)MAXROWS*128];
__device__ float g_q[(size_t)MAXROWS*128];
__device__ float g_k[(size_t)MAXROWS*128];
__device__ float g_v[(size_t)MAXROWS*128];

// fragment-packed tf32 weights
#define W_EW  0
#define W_Q   16384
#define W_K   32768
#define W_V   49152
#define W_QS  65536
#define W_AFC 81920
#define W_F1  98304
#define W_F2  163840
#define W_TOT 229376
__device__ float g_wbuf[W_TOT];

__device__ __forceinline__ float gelu_exact(float x) {
    return 0.5f * x * (1.0f + erff(x * 0.7071067811865475f));
}
__device__ __forceinline__ float to_tf32(float x) {
    unsigned u;
    asm("cvt.rna.tf32.f32 %0, %1;" : "=r"(u) : "f"(x));
    return __uint_as_float(u);
}
__device__ __forceinline__ void mma_tf32(float d[4], const float a[4], const float b[2]) {
    asm volatile(
        "mma.sync.aligned.m16n8k8.row.col.f32.tf32.tf32.f32 "
        "{%0,%1,%2,%3}, {%4,%5,%6,%7}, {%8,%9}, {%0,%1,%2,%3};"
        : "+f"(d[0]), "+f"(d[1]), "+f"(d[2]), "+f"(d[3])
        : "r"(__float_as_uint(a[0])), "r"(__float_as_uint(a[1])),
          "r"(__float_as_uint(a[2])), "r"(__float_as_uint(a[3])),
          "r"(__float_as_uint(b[0])), "r"(__float_as_uint(b[1])));
}

#define ACC_ZERO2(acc) do { _Pragma("unroll") for (int _m=0;_m<2;_m++) _Pragma("unroll") for (int _n=0;_n<4;_n++) { acc[_m][_n][0]=0.f;acc[_m][_n][1]=0.f;acc[_m][_n][2]=0.f;acc[_m][_n][3]=0.f; } } while(0)

__device__ __forceinline__ void cpa16(float* dst, const float* src) {
    unsigned u = (unsigned)__cvta_generic_to_shared(dst);
    asm volatile("cp.async.cg.shared.global [%0], [%1], 16;\n" :: "r"(u), "l"(src));
}
#define CP_COMMIT() asm volatile("cp.async.commit_group;\n")
#define CP_WAIT(n)  asm volatile("cp.async.wait_group %0;\n" :: "n"(n))

// stage one packed 32-k chunk (4096 floats, contiguous) via cp.async
__device__ __forceinline__ void stageWp(float* dst, const float* __restrict__ W,
                                        int kc, int tid) {
#pragma unroll
    for (int j = 0; j < 4; j++) {
        int idx = (tid + j * NT) << 2;
        cpa16(dst + idx, W + kc * WCH + idx);
    }
}

// M=64 tile GEMM on fragment-packed weights: acc[2][4][4], warp grid 2(M)x4(N)
__device__ __forceinline__ void gemm128p(float acc[2][4][4], const float* sAct,
                                         const float* __restrict__ Wg,
                                         float* sWbuf, int tid) {
    const int lane = tid & 31, w = tid >> 5;
    const int mg = w & 1, ng = w >> 1;
    const int qr = lane >> 2, qc = lane & 3;
    stageWp(sWbuf, Wg, 0, tid);
    CP_COMMIT();
#pragma unroll
    for (int kc = 0; kc < 4; kc++) {
        const float* sw = sWbuf + (kc & 1) * WCH;
        if (kc < 3) {
            stageWp(sWbuf + ((kc + 1) & 1) * WCH, Wg, kc + 1, tid);
            CP_COMMIT();
            CP_WAIT(1);
        } else {
            CP_WAIT(0);
        }
        __syncthreads();
#pragma unroll
        for (int ks2 = 0; ks2 < 2; ks2++) {
            float4 bf4[4];
#pragma unroll
            for (int nt = 0; nt < 4; nt++) {
                int n = (ng * 4 + nt) * 8 + qr;
                bf4[nt] = *(const float4*)(sw + ks2 * 2048 + n * 16 + qc * 4);
            }
#pragma unroll
            for (int sub = 0; sub < 2; sub++) {
                const int k0 = kc * 32 + ks2 * 16 + sub * 8;
                float af[2][4];
#pragma unroll
                for (int mt = 0; mt < 2; mt++) {
                    const float* ap = sAct + ((mg * 2 + mt) * 16 + qr) * LDA + k0 + qc;
                    af[mt][0] = ap[0];
                    af[mt][1] = ap[8 * LDA];
                    af[mt][2] = ap[4];
                    af[mt][3] = ap[8 * LDA + 4];
                }
#pragma unroll
                for (int nt = 0; nt < 4; nt++) {
                    float b2[2];
                    b2[0] = sub ? bf4[nt].z : bf4[nt].x;
                    b2[1] = sub ? bf4[nt].w : bf4[nt].y;
                    mma_tf32(acc[0][nt], af[0], b2);
                    mma_tf32(acc[1][nt], af[1], b2);
                }
            }
        }
        __syncthreads();
    }
}

__device__ __forceinline__ void store_direct(float* __restrict__ g, long row0,
                                             float acc[2][4][4], int tid) {
    const int lane = tid & 31, w = tid >> 5;
    const int mg = w & 1, ng = w >> 1;
    const int qr = lane >> 2, qc = lane & 3;
#pragma unroll
    for (int mt = 0; mt < 2; mt++) {
        long r = row0 + (mg * 2 + mt) * 16 + qr;
#pragma unroll
        for (int nt = 0; nt < 4; nt++) {
            int c = (ng * 4 + nt) * 8 + qc * 2;
            float2 a0; a0.x = to_tf32(acc[mt][nt][0]); a0.y = to_tf32(acc[mt][nt][1]);
            float2 a1; a1.x = to_tf32(acc[mt][nt][2]); a1.y = to_tf32(acc[mt][nt][3]);
            *(float2*)(g + (size_t)r * 128 + c) = a0;
            *(float2*)(g + (size_t)(r + 8) * 128 + c) = a1;
        }
    }
}

// ------------------- kernel 0: pack weights to fragment order (tf32) --------
__global__ void k_prep(const float* __restrict__ e_w, const float* __restrict__ wq,
                       const float* __restrict__ wk, const float* __restrict__ wv,
                       const float* __restrict__ wq_src, const float* __restrict__ afc_w,
                       const float* __restrict__ f_w1, const float* __restrict__ f_w2)
{
    int i = blockIdx.x * 256 + threadIdx.x;
    if (i >= W_TOT) return;
    const float* src; int rel; int ldw = 128; int kbase = 0; int nbase = 0;
    if      (i < W_Q)   { src = e_w;    rel = i - W_EW; }
    else if (i < W_K)   { src = wq;     rel = i - W_Q; }
    else if (i < W_V)   { src = wk;     rel = i - W_K; }
    else if (i < W_QS)  { src = wv;     rel = i - W_V; }
    else if (i < W_AFC) { src = wq_src; rel = i - W_QS; }
    else if (i < W_F1)  { src = afc_w;  rel = i - W_AFC; }
    else if (i < W_F2)  { src = f_w1;   rel = i - W_F1;
                          int c = rel / 16384; rel -= c * 16384; ldw = 512; nbase = c * 128; }
    else                { src = f_w2;   rel = i - W_F2;
                          int c = rel / 16384; rel -= c * 16384; kbase = c * 128; }
    int kc = rel >> 12;
    int within = rel & 4095;
    int ks2 = within >> 11;
    int remn = within & 2047;
    int n = remn >> 4;
    int rem2 = remn & 15;
    int qc = rem2 >> 2;
    int e = rem2 & 3;
    int k = kc * 32 + ks2 * 16 + qc + (e & 1) * 4 + (e >> 1) * 8;
    g_wbuf[i] = to_tf32(src[(size_t)(kbase + k) * ldw + nbase + n]);
}

// ------------------- kernel 1: z + qkv fused (M=64 tiles) -------------------
__global__ __launch_bounds__(NT, 2)
void k_zqkv(const float* __restrict__ nh, const float* __restrict__ t,
            const float* __restrict__ t_now, const float* __restrict__ ef,
            const float* __restrict__ bfreq, const float* __restrict__ phase,
            const float* __restrict__ e_b, long totrows)
{
    extern __shared__ float sm[];
    float* sA = sm;
    float* sZ = sm + 64 * LDA;
    float* sW = sZ + 64 * LDA;
    const int tid = threadIdx.x;
    const long row0 = (long)blockIdx.x * 64;
    const int rv = (int)min((long)64, totrows - row0);

#pragma unroll
    for (int j = 0; j < 8; j++) {
        int idx = tid + j * NT;
        int r = idx >> 5;
        int c4 = (idx & 31) << 2;
        float4 v = make_float4(0.f, 0.f, 0.f, 0.f);
        if (r < rv) v = *(const float4*)(ef + (size_t)(row0 + r) * 128 + c4);
        float4 o;
        o.x = to_tf32(v.x); o.y = to_tf32(v.y); o.z = to_tf32(v.z); o.w = to_tf32(v.w);
        *(float4*)(sA + r * LDA + c4) = o;
    }
    __syncthreads();

    float acc[2][4][4];
    ACC_ZERO2(acc);
    gemm128p(acc, sA, g_wbuf + W_EW, sW, tid);

    const float tn = t_now[0];
    const int lane = tid & 31, w = tid >> 5;
    const int mg = w & 1, ng = w >> 1;
    const int qr = lane >> 2, qc = lane & 3;
#pragma unroll
    for (int mt = 0; mt < 2; mt++) {
        int lr0 = (mg * 2 + mt) * 16 + qr;
#pragma unroll
        for (int hh = 0; hh < 2; hh++) {
            int lr = lr0 + hh * 8;
            long gr = row0 + lr;
            bool ok = (lr < rv);
            float tv = ok ? t[gr] : 0.f;
#pragma unroll
            for (int nt = 0; nt < 4; nt++) {
                int c = (ng * 4 + nt) * 8 + qc * 2;
#pragma unroll
                for (int p = 0; p < 2; p++) {
                    int cc = c + p;
                    float zv = 0.f;
                    if (ok) {
                        float g = gelu_exact(acc[mt][nt][hh * 2 + p] + e_b[cc]);
                        float te = cosf((tn - tv) * bfreq[cc] + phase[cc]);
                        zv = to_tf32(nh[(size_t)gr * 128 + cc] + g + te);
                        g_z[(size_t)gr * 128 + cc] = zv;
                    }
                    sZ[lr * LDA + cc] = zv;
                }
            }
        }
    }
    __syncthreads();

    ACC_ZERO2(acc); gemm128p(acc, sZ, g_wbuf + W_Q, sW, tid);
    if (rv == 64) store_direct(g_q, row0, acc, tid);
    else {
#pragma unroll
        for (int mt = 0; mt < 2; mt++) {
            int lr0 = (mg * 2 + mt) * 16 + qr;
#pragma unroll
            for (int hh = 0; hh < 2; hh++) {
                int lr = lr0 + hh * 8;
                if (lr < rv)
#pragma unroll
                    for (int nt = 0; nt < 4; nt++) {
                        int c = (ng * 4 + nt) * 8 + qc * 2;
                        float2 a; a.x = to_tf32(acc[mt][nt][hh*2]); a.y = to_tf32(acc[mt][nt][hh*2+1]);
                        *(float2*)(g_q + (size_t)(row0 + lr) * 128 + c) = a;
                    }
            }
        }
    }
    ACC_ZERO2(acc); gemm128p(acc, sZ, g_wbuf + W_K, sW, tid);
    if (rv == 64) store_direct(g_k, row0, acc, tid);
    ACC_ZERO2(acc); gemm128p(acc, sZ, g_wbuf + W_V, sW, tid);
    if (rv == 64) store_direct(g_v, row0, acc, tid);
}

// ------------------- kernel 2: self_q -------------------
__global__ __launch_bounds__(NT, 2)
void k_selfq(int Ntot)
{
    extern __shared__ float sm[];
    float* sA = sm;
    float* sW = sm + 64 * LDA;
    const int tid = threadIdx.x;
    const int n0 = blockIdx.x * 64;
    const int rv = min(64, Ntot - n0);
#pragma unroll
    for (int j = 0; j < 8; j++) {
        int idx = tid + j * NT;
        int r = idx >> 5;
        int c4 = (idx & 31) << 2;
        if (r < rv) cpa16(sA + r * LDA + c4, g_z + ((size_t)(n0 + r) * 20 + 19) * 128 + c4);
        else *(float4*)(sA + r * LDA + c4) = make_float4(0.f, 0.f, 0.f, 0.f);
    }
    CP_COMMIT();
    float acc[2][4][4];
    ACC_ZERO2(acc);
    gemm128p(acc, sA, g_wbuf + W_QS, sW, tid);
    const int lane = tid & 31, w = tid >> 5;
    const int mg = w & 1, ng = w >> 1;
    const int qr = lane >> 2, qc = lane & 3;
#pragma unroll
    for (int mt = 0; mt < 2; mt++) {
        int r = (mg * 2 + mt) * 16 + qr;
#pragma unroll
        for (int nt = 0; nt < 4; nt++) {
            int c = (ng * 4 + nt) * 8 + qc * 2;
#pragma unroll
            for (int hh = 0; hh < 2; hh++) {
                int rr = r + hh * 8;
                if (rr < rv) {
                    size_t go = ((size_t)(n0 + rr) * 20 + 19) * 128 + c;
                    float2 v;
                    v.x = to_tf32(acc[mt][nt][hh * 2]);
                    v.y = to_tf32(acc[mt][nt][hh * 2 + 1]);
                    *(float2*)(g_q + go) = v;
                    *(float2*)(g_k + go) = v;
                    *(float2*)(g_v + go) = v;
                }
            }
        }
    }
}

// -------- kernel 3: attention + attn_fc + LN + FFN + LN + fuse + out --------
#define AHS 36
#define ARS 144
__global__ __launch_bounds__(NT, 2)
void k_anf(const float* __restrict__ afc_b, const float* __restrict__ aln_g,
           const float* __restrict__ aln_b,
           const float* __restrict__ f_b1, const float* __restrict__ f_b2,
           const float* __restrict__ fln_g, const float* __restrict__ fln_b,
           const float* __restrict__ f2n_w, const float* __restrict__ f2n_b,
           const float* __restrict__ oln_g, const float* __restrict__ oln_b,
           const float* __restrict__ nh, float* __restrict__ out, int Ntot)
{
    extern __shared__ float sm[];
    float* sK  = sm;                       // [60][144]; later sO/x [64][132]
    float* sV  = sm + 60 * ARS;            // [60][144]; later sH [64][132]
    float* sW  = sm + 120 * ARS;           // 2*WCH
    float* scr = sW + 2 * WCH;             // 1024
    const int tid = threadIdx.x;
    const int nb0 = blockIdx.x * 3;
    const int nodes_here = min(3, Ntot - nb0);
    const int rows = nodes_here * 20;
    const size_t gbase = (size_t)nb0 * 20 * 128;

    // ---- stage K/V conflict-free ----
    for (int i = tid; i < rows * 32; i += NT) {
        int r = i >> 5, c4 = (i & 31) << 2;
        int hd = c4 >> 5, ci = c4 & 31;
        *(float4*)(sK + r * ARS + hd * AHS + ci) = *(const float4*)(g_k + gbase + (size_t)r * 128 + c4);
        *(float4*)(sV + r * ARS + hd * AHS + ci) = *(const float4*)(g_v + gbase + (size_t)r * 128 + c4);
    }
    __syncthreads();

    // ---- attention (q from gmem, p/oacc in regs) ----
    const int node = tid / 80, h = (tid / 20) % 4, qi = tid % 20;
    const bool active = tid < nodes_here * 80;
    float oacc[32];
    if (active) {
        float qreg[32];
        const float* qp = g_q + gbase + (size_t)(node * 20 + qi) * 128 + h * 32;
#pragma unroll
        for (int j = 0; j < 8; j++) {
            float4 v = *(const float4*)(qp + j * 4);
            qreg[4*j] = v.x; qreg[4*j+1] = v.y; qreg[4*j+2] = v.z; qreg[4*j+3] = v.w;
        }
        float p[20];
#pragma unroll
        for (int ki = 0; ki < 20; ki++) {
            const float* kp = sK + (node * 20 + ki) * ARS + h * AHS;
            float s = 0.f;
#pragma unroll
            for (int j = 0; j < 8; j++) {
                float4 kv = *(const float4*)(kp + j * 4);
                s += qreg[4*j] * kv.x + qreg[4*j+1] * kv.y + qreg[4*j+2] * kv.z + qreg[4*j+3] * kv.w;
            }
            p[ki] = s * 0.17677669529663687f;
        }
        float m = p[0];
#pragma unroll
        for (int ki = 1; ki < 20; ki++) m = fmaxf(m, p[ki]);
        float ssum = 0.f;
#pragma unroll
        for (int ki = 0; ki < 20; ki++) { p[ki] = expf(p[ki] - m); ssum += p[ki]; }
        float inv = 1.f / ssum;
#pragma unroll
        for (int ki = 0; ki < 20; ki++) p[ki] *= inv;
#pragma unroll
        for (int j = 0; j < 32; j++) oacc[j] = 0.f;
#pragma unroll
        for (int ki = 0; ki < 20; ki++) {
            float pw = p[ki];
            const float* vp = sV + (node * 20 + ki) * ARS + h * AHS;
#pragma unroll
            for (int j = 0; j < 8; j++) {
                float4 vv = *(const float4*)(vp + j * 4);
                oacc[4*j]   += pw * vv.x; oacc[4*j+1] += pw * vv.y;
                oacc[4*j+2] += pw * vv.z; oacc[4*j+3] += pw * vv.w;
            }
        }
    }
    __syncthreads();   // all K/V reads done; alias regions

    float* sO = sK;    // [64][LDA] — O, then x
    float* sH = sV;    // [64][LDA] — FFN hidden, then output rows
    if (active) {
        float* op = sO + (node * 20 + qi) * LDA + h * 32;
#pragma unroll
        for (int j = 0; j < 8; j++) {
            float4 v;
            v.x = to_tf32(oacc[4*j]);   v.y = to_tf32(oacc[4*j+1]);
            v.z = to_tf32(oacc[4*j+2]); v.w = to_tf32(oacc[4*j+3]);
            *(float4*)(op + j * 4) = v;
        }
    }
    __syncthreads();   // (M-pad rows of sO hold stale K data; M rows are independent)

    // ---- attn_fc GEMM ----
    float acc[2][4][4];
    ACC_ZERO2(acc);
    gemm128p(acc, sO, g_wbuf + W_AFC, sW, tid);

    const int lane = tid & 31, w = tid >> 5;
    const int mg = w & 1, ng = w >> 1;
    const int qr = lane >> 2, qc = lane & 3;
#pragma unroll
    for (int mt = 0; mt < 2; mt++) {
        int r = (mg * 2 + mt) * 16 + qr;
#pragma unroll
        for (int nt = 0; nt < 4; nt++) {
            int c = (ng * 4 + nt) * 8 + qc * 2;
            sO[r * LDA + c]           = acc[mt][nt][0];
            sO[r * LDA + c + 1]       = acc[mt][nt][1];
            sO[(r + 8) * LDA + c]     = acc[mt][nt][2];
            sO[(r + 8) * LDA + c + 1] = acc[mt][nt][3];
        }
    }
    __syncthreads();

    // + afc_b + z residual (coalesced z read)
    for (int i = tid; i < 64 * 128; i += NT) {
        int r = i >> 7, d = i & 127;
        if (r < rows) sO[r * LDA + d] += afc_b[d] + g_z[gbase + (size_t)r * 128 + d];
    }
    __syncthreads();

    // ---- attn LN -> x (tf32, in place in sO) ----
    if (tid < rows) {
        float m = 0.f;
#pragma unroll 8
        for (int dd = 0; dd < 128; dd++) m += sO[tid * LDA + ((dd + tid) & 127)];
        m *= (1.0f / 128.0f);
        float v = 0.f;
#pragma unroll 8
        for (int dd = 0; dd < 128; dd++) { float x = sO[tid * LDA + ((dd + tid) & 127)] - m; v += x * x; }
        v *= (1.0f / 128.0f);
        scr[tid] = m;
        scr[64 + tid] = rsqrtf(v + 1e-5f);
    }
    __syncthreads();
    for (int i = tid; i < 64 * 128; i += NT) {
        int r = i >> 7, d = i & 127;
        if (r < rows) {
            float y = (sO[r * LDA + d] - scr[r]) * scr[64 + r] * aln_g[d] + aln_b[d];
            sO[r * LDA + d] = to_tf32(y);
        }
    }
    __syncthreads();

    // ---- FFN: 4 column chunks, x2 accumulated in registers ----
    float x2[2][4][4];
    ACC_ZERO2(x2);
    for (int c = 0; c < 4; c++) {
        ACC_ZERO2(acc);
        gemm128p(acc, sO, g_wbuf + W_F1 + c * 16384, sW, tid);
#pragma unroll
        for (int mt = 0; mt < 2; mt++) {
            int r = (mg * 2 + mt) * 16 + qr;
#pragma unroll
            for (int nt = 0; nt < 4; nt++) {
                int col = (ng * 4 + nt) * 8 + qc * 2;
                float b0 = f_b1[c * 128 + col], b1 = f_b1[c * 128 + col + 1];
                sH[r * LDA + col]           = to_tf32(fmaxf(acc[mt][nt][0] + b0, 0.f));
                sH[r * LDA + col + 1]       = to_tf32(fmaxf(acc[mt][nt][1] + b1, 0.f));
                sH[(r + 8) * LDA + col]     = to_tf32(fmaxf(acc[mt][nt][2] + b0, 0.f));
                sH[(r + 8) * LDA + col + 1] = to_tf32(fmaxf(acc[mt][nt][3] + b1, 0.f));
            }
        }
        __syncthreads();
        gemm128p(x2, sH, g_wbuf + W_F2 + c * 16384, sW, tid);
    }

    // x2 + b2 + x -> sH
#pragma unroll
    for (int mt = 0; mt < 2; mt++) {
        int r = (mg * 2 + mt) * 16 + qr;
#pragma unroll
        for (int nt = 0; nt < 4; nt++) {
            int col = (ng * 4 + nt) * 8 + qc * 2;
            float b0 = f_b2[col], b1 = f_b2[col + 1];
            sH[r * LDA + col]           = x2[mt][nt][0] + b0 + sO[r * LDA + col];
            sH[r * LDA + col + 1]       = x2[mt][nt][1] + b1 + sO[r * LDA + col + 1];
            sH[(r + 8) * LDA + col]     = x2[mt][nt][2] + b0 + sO[(r + 8) * LDA + col];
            sH[(r + 8) * LDA + col + 1] = x2[mt][nt][3] + b1 + sO[(r + 8) * LDA + col + 1];
        }
    }
    __syncthreads();

    // ---- FFN LN (in place in sH) ----
    if (tid < rows) {
        float m = 0.f;
#pragma unroll 8
        for (int dd = 0; dd < 128; dd++) m += sH[tid * LDA + ((dd + tid) & 127)];
        m *= (1.0f / 128.0f);
        float v = 0.f;
#pragma unroll 8
        for (int dd = 0; dd < 128; dd++) { float x = sH[tid * LDA + ((dd + tid) & 127)] - m; v += x * x; }
        v *= (1.0f / 128.0f);
        scr[tid] = m;
        scr[64 + tid] = rsqrtf(v + 1e-5f);
    }
    __syncthreads();
    for (int i = tid; i < rows * 128; i += NT) {
        int r = i >> 7, d = i & 127;
        sH[r * LDA + d] = (sH[r * LDA + d] - scr[r]) * scr[64 + r] * fln_g[d] + fln_b[d];
    }
    __syncthreads();

    // ---- fuse: neighborhood mean, fea2node, out LN ----
    float* sNe = scr + 128;
    float* sY  = scr + 512;
    for (int i = tid; i < nodes_here * 128; i += NT) {
        int nn = i >> 7, d = i & 127;
        float s = 0.f;
#pragma unroll
        for (int k = 0; k < 19; k++) s += sH[(nn * 20 + k) * LDA + d];
        sNe[i] = s * (1.0f / 19.0f);
    }
    __syncthreads();
    for (int idx = tid; idx < nodes_here * 128; idx += NT) {
        int nn = idx >> 7, d = idx & 127;
        const float* selfr = sH + (nn * 20 + 19) * LDA;
        const float* ne = sNe + nn * 128;
        float a = 0.f;
#pragma unroll 4
        for (int e = 0; e < 128; e++) a += selfr[e] * f2n_w[e * 128 + d];
#pragma unroll 4
        for (int e = 0; e < 128; e++) a += ne[e] * f2n_w[(128 + e) * 128 + d];
        float y = gelu_exact(a + f2n_b[d])
                + nh[((size_t)(nb0 + nn) * 20 + 19) * 128 + d];
        sY[idx] = y;
    }
    __syncthreads();
    if (tid < nodes_here) {
        float m = 0.f;
        for (int d = 0; d < 128; d++) m += sY[tid * 128 + d];
        m *= (1.0f / 128.0f);
        float v = 0.f;
        for (int d = 0; d < 128; d++) { float x = sY[tid * 128 + d] - m; v += x * x; }
        v *= (1.0f / 128.0f);
        scr[896 + tid] = m;
        scr[900 + tid] = rsqrtf(v + 1e-5f);
    }
    __syncthreads();
    for (int idx = tid; idx < nodes_here * 128; idx += NT) {
        int nn = idx >> 7, d = idx & 127;
        float y = (sY[idx] - scr[896 + nn]) * scr[900 + nn];
        out[(size_t)(nb0 + nn) * 128 + d] = y * oln_g[d] + oln_b[d];
    }
}

// ------------------- launch -------------------
#define SM_ZQKV ((2 * 64 * LDA + 2 * WCH) * 4)
#define SM_AB   ((64 * LDA + 2 * WCH) * 4)
#define SM_ANF  ((120 * ARS + 2 * WCH + 1024) * 4)

extern "C" void kernel_launch(void* const* d_in, const int* in_sizes, int n_in,
                              void* d_out, int out_size) {
    (void)n_in; (void)out_size;
    const float* nh      = (const float*)d_in[0];
    const float* t       = (const float*)d_in[1];
    const float* t_now   = (const float*)d_in[2];
    const float* ef      = (const float*)d_in[3];
    const float* bfreq   = (const float*)d_in[4];
    const float* phase   = (const float*)d_in[5];
    const float* e_w     = (const float*)d_in[6];
    const float* e_b     = (const float*)d_in[7];
    const float* wq      = (const float*)d_in[8];
    const float* wk      = (const float*)d_in[9];
    const float* wv      = (const float*)d_in[10];
    const float* wq_src  = (const float*)d_in[11];
    const float* afc_w   = (const float*)d_in[12];
    const float* afc_b   = (const float*)d_in[13];
    const float* aln_g   = (const float*)d_in[14];
    const float* aln_b   = (const float*)d_in[15];
    const float* f_w1    = (const float*)d_in[16];
    const float* f_b1    = (const float*)d_in[17];
    const float* f_w2    = (const float*)d_in[18];
    const float* f_b2    = (const float*)d_in[19];
    const float* fln_g   = (const float*)d_in[20];
    const float* fln_b   = (const float*)d_in[21];
    const float* f2n_w   = (const float*)d_in[22];
    const float* f2n_b   = (const float*)d_in[23];
    const float* oln_g   = (const float*)d_in[24];
    const float* oln_b   = (const float*)d_in[25];
    float* out = (float*)d_out;

    const int N = in_sizes[0] / 2560;
    const long totrows = (long)N * 20;
    const int gM = (int)((totrows + 63) / 64);

    cudaFuncSetAttribute(k_zqkv,  cudaFuncAttributeMaxDynamicSharedMemorySize, SM_ZQKV);
    cudaFuncSetAttribute(k_selfq, cudaFuncAttributeMaxDynamicSharedMemorySize, SM_AB);
    cudaFuncSetAttribute(k_anf,   cudaFuncAttributeMaxDynamicSharedMemorySize, SM_ANF);

    k_prep<<<(W_TOT + 255) / 256, 256>>>(e_w, wq, wk, wv, wq_src, afc_w, f_w1, f_w2);
    k_zqkv<<<gM, NT, SM_ZQKV>>>(nh, t, t_now, ef, bfreq, phase, e_b, totrows);
    k_selfq<<<(N + 63) / 64, NT, SM_AB>>>(N);
    k_anf<<<(N + 2) / 3, NT, SM_ANF>>>(afc_b, aln_g, aln_b,
                                       f_b1, f_b2, fln_g, fln_b,
                                       f2n_w, f2n_b, oln_g, oln_b, nh, out, N);
}

// round 14
// speedup vs baseline: 1.3987x; 1.3122x over previous
#include <cuda_runtime.h>
#include <cuda_fp16.h>
#include <math.h>

#define LDH 136       // half stride for activation tiles
#define LDA 132       // fp32 scratch stride
#define NT 256
#define WCHH 4096     // halfs per packed 32-k weight chunk (8KB)
#define MAXROWS (20000*20)

__device__ half g_z[(size_t)MAXROWS*128];
__device__ half g_q[(size_t)MAXROWS*128];
__device__ half g_k[(size_t)MAXROWS*128];
__device__ half g_v[(size_t)MAXROWS*128];

// fragment-packed fp16 weights (element-count offsets)
#define W_EW  0
#define W_Q   16384
#define W_K   32768
#define W_V   49152
#define W_QS  65536
#define W_AFC 81920
#define W_F1  98304
#define W_F2  163840
#define W_TOT 229376
__device__ half g_wbuf[W_TOT];

__device__ __forceinline__ float gelu_exact(float x) {
    return 0.5f * x * (1.0f + erff(x * 0.7071067811865475f));
}

__device__ __forceinline__ void mma_f16(float d[4], const unsigned a[4], const unsigned b[2]) {
    asm volatile(
        "mma.sync.aligned.m16n8k16.row.col.f32.f16.f16.f32 "
        "{%0,%1,%2,%3}, {%4,%5,%6,%7}, {%8,%9}, {%0,%1,%2,%3};"
        : "+f"(d[0]), "+f"(d[1]), "+f"(d[2]), "+f"(d[3])
        : "r"(a[0]), "r"(a[1]), "r"(a[2]), "r"(a[3]), "r"(b[0]), "r"(b[1]));
}

#define ACC_ZERO2(acc) do { _Pragma("unroll") for (int _m=0;_m<2;_m++) _Pragma("unroll") for (int _n=0;_n<4;_n++) { acc[_m][_n][0]=0.f;acc[_m][_n][1]=0.f;acc[_m][_n][2]=0.f;acc[_m][_n][3]=0.f; } } while(0)

__device__ __forceinline__ void cpa16h(half* dst, const half* src) {
    unsigned u = (unsigned)__cvta_generic_to_shared(dst);
    asm volatile("cp.async.cg.shared.global [%0], [%1], 16;\n" :: "r"(u), "l"(src));
}
#define CP_COMMIT() asm volatile("cp.async.commit_group;\n")
#define CP_WAIT(n)  asm volatile("cp.async.wait_group %0;\n" :: "n"(n))

// stage one packed 32-k chunk (4096 halfs = 8KB, contiguous)
__device__ __forceinline__ void stageWh(half* dst, const half* __restrict__ W,
                                        int kc, int tid) {
#pragma unroll
    for (int j = 0; j < 2; j++) {
        int idx = (tid + j * NT) << 3;       // 8 halfs = 16B per op, 512 ops
        cpa16h(dst + idx, W + kc * WCHH + idx);
    }
}

// M=64 fp16 GEMM on fragment-packed weights: acc[2][4][4] fp32, warp grid 2(M)x4(N)
__device__ __forceinline__ void gemmH(float acc[2][4][4], const half* actH,
                                      const half* __restrict__ Wg,
                                      half* sWbuf, int tid) {
    const int lane = tid & 31, w = tid >> 5;
    const int mg = w & 1, ng = w >> 1;
    const int g = lane >> 2, t = lane & 3;
    stageWh(sWbuf, Wg, 0, tid);
    CP_COMMIT();
#pragma unroll
    for (int kc = 0; kc < 4; kc++) {
        const half* sw = sWbuf + (kc & 1) * WCHH;
        if (kc < 3) {
            stageWh(sWbuf + ((kc + 1) & 1) * WCHH, Wg, kc + 1, tid);
            CP_COMMIT();
            CP_WAIT(1);
        } else {
            CP_WAIT(0);
        }
        __syncthreads();
#pragma unroll
        for (int ks2 = 0; ks2 < 2; ks2++) {
            unsigned bb[4][2];
#pragma unroll
            for (int nt = 0; nt < 4; nt++) {
                int n = ng * 32 + nt * 8 + g;
                uint2 bv = *(const uint2*)(sw + ks2 * 2048 + n * 16 + t * 4);
                bb[nt][0] = bv.x; bb[nt][1] = bv.y;
            }
            const int k0 = kc * 32 + ks2 * 16;
#pragma unroll
            for (int mt = 0; mt < 2; mt++) {
                const half* ap = actH + ((mg * 2 + mt) * 16 + g) * LDH + k0 + 2 * t;
                unsigned a4[4];
                a4[0] = *(const unsigned*)(ap);
                a4[1] = *(const unsigned*)(ap + 8 * LDH);
                a4[2] = *(const unsigned*)(ap + 8);
                a4[3] = *(const unsigned*)(ap + 8 * LDH + 8);
#pragma unroll
                for (int nt = 0; nt < 4; nt++) mma_f16(acc[mt][nt], a4, bb[nt]);
            }
        }
        __syncthreads();
    }
}

// ------------------- kernel 0: pack weights to fp16 fragment order ----------
// per 128x128 matrix: 4 chunks of 4096 halfs; within chunk: [ks2][n][t][e],
// k = kc*32 + ks2*16 + 2t + (e&1) + 8*(e>>1)
__global__ void k_prep(const float* __restrict__ e_w, const float* __restrict__ wq,
                       const float* __restrict__ wk, const float* __restrict__ wv,
                       const float* __restrict__ wq_src, const float* __restrict__ afc_w,
                       const float* __restrict__ f_w1, const float* __restrict__ f_w2)
{
    int i = blockIdx.x * 256 + threadIdx.x;
    if (i >= W_TOT) return;
    const float* src; int rel; int ldw = 128; int kbase = 0; int nbase = 0;
    if      (i < W_Q)   { src = e_w;    rel = i - W_EW; }
    else if (i < W_K)   { src = wq;     rel = i - W_Q; }
    else if (i < W_V)   { src = wk;     rel = i - W_K; }
    else if (i < W_QS)  { src = wv;     rel = i - W_V; }
    else if (i < W_AFC) { src = wq_src; rel = i - W_QS; }
    else if (i < W_F1)  { src = afc_w;  rel = i - W_AFC; }
    else if (i < W_F2)  { src = f_w1;   rel = i - W_F1;
                          int c = rel / 16384; rel -= c * 16384; ldw = 512; nbase = c * 128; }
    else                { src = f_w2;   rel = i - W_F2;
                          int c = rel / 16384; rel -= c * 16384; kbase = c * 128; }
    int kc = rel >> 12;
    int within = rel & 4095;
    int ks2 = within >> 11;
    int remn = within & 2047;
    int n = remn >> 4;
    int rem2 = remn & 15;
    int t = rem2 >> 2;
    int e = rem2 & 3;
    int k = kc * 32 + ks2 * 16 + 2 * t + (e & 1) + 8 * (e >> 1);
    g_wbuf[i] = __float2half_rn(src[(size_t)(kbase + k) * ldw + nbase + n]);
}

// ------------------- kernel 1: z + qkv fused -------------------
__global__ __launch_bounds__(NT, 2)
void k_zqkv(const float* __restrict__ nh, const float* __restrict__ t,
            const float* __restrict__ t_now, const float* __restrict__ ef,
            const float* __restrict__ bfreq, const float* __restrict__ phase,
            const float* __restrict__ e_b, long totrows)
{
    extern __shared__ char smx[];
    half* sA = (half*)smx;                 // 64*LDH
    half* sZ = sA + 64 * LDH;              // 64*LDH
    half* sW = sZ + 64 * LDH;              // 2*WCHH
    const int tid = threadIdx.x;
    const long row0 = (long)blockIdx.x * 64;
    const int rv = (int)min((long)64, totrows - row0);

    // stage ef (fp32 -> half)
#pragma unroll
    for (int j = 0; j < 8; j++) {
        int idx = tid + j * NT;            // 2048 = 64 rows x 32 segs
        int r = idx >> 5;
        int c4 = (idx & 31) << 2;
        float4 v = make_float4(0.f, 0.f, 0.f, 0.f);
        if (r < rv) v = *(const float4*)(ef + (size_t)(row0 + r) * 128 + c4);
        half2* dp = (half2*)(sA + r * LDH + c4);
        dp[0] = __floats2half2_rn(v.x, v.y);
        dp[1] = __floats2half2_rn(v.z, v.w);
    }
    __syncthreads();

    float acc[2][4][4];
    ACC_ZERO2(acc);
    gemmH(acc, sA, g_wbuf + W_EW, sW, tid);

    const float tn = t_now[0];
    const int lane = tid & 31, w = tid >> 5;
    const int mg = w & 1, ng = w >> 1;
    const int qr = lane >> 2, qc = lane & 3;
#pragma unroll
    for (int mt = 0; mt < 2; mt++) {
#pragma unroll
        for (int hh = 0; hh < 2; hh++) {
            int lr = (mg * 2 + mt) * 16 + qr + hh * 8;
            long gr = row0 + lr;
            bool ok = (lr < rv);
            float tv = ok ? t[gr] : 0.f;
#pragma unroll
            for (int nt = 0; nt < 4; nt++) {
                int cc = ng * 32 + nt * 8 + qc * 2;
                float zv0 = 0.f, zv1 = 0.f;
                if (ok) {
                    float g0 = gelu_exact(acc[mt][nt][hh * 2] + e_b[cc]);
                    float g1 = gelu_exact(acc[mt][nt][hh * 2 + 1] + e_b[cc + 1]);
                    zv0 = nh[(size_t)gr * 128 + cc] + g0 + cosf((tn - tv) * bfreq[cc] + phase[cc]);
                    zv1 = nh[(size_t)gr * 128 + cc + 1] + g1 + cosf((tn - tv) * bfreq[cc + 1] + phase[cc + 1]);
                }
                half2 hz = __floats2half2_rn(zv0, zv1);
                if (ok) *(half2*)(g_z + (size_t)gr * 128 + cc) = hz;
                *(half2*)(sZ + lr * LDH + cc) = hz;
            }
        }
    }
    // first sync inside next gemm orders sZ writes before reads

#pragma unroll
    for (int which = 0; which < 3; which++) {
        const half* Wg = (which == 0) ? g_wbuf + W_Q : (which == 1) ? g_wbuf + W_K : g_wbuf + W_V;
        half* dst = (which == 0) ? g_q : (which == 1) ? g_k : g_v;
        ACC_ZERO2(acc);
        gemmH(acc, sZ, Wg, sW, tid);
#pragma unroll
        for (int mt = 0; mt < 2; mt++)
#pragma unroll
            for (int hh = 0; hh < 2; hh++) {
                int lr = (mg * 2 + mt) * 16 + qr + hh * 8;
                if (lr < rv)
#pragma unroll
                    for (int nt = 0; nt < 4; nt++) {
                        int cc = ng * 32 + nt * 8 + qc * 2;
                        *(half2*)(dst + (size_t)(row0 + lr) * 128 + cc) =
                            __floats2half2_rn(acc[mt][nt][hh * 2], acc[mt][nt][hh * 2 + 1]);
                    }
            }
    }
}

// ------------------- kernel 2: self_q -------------------
__global__ __launch_bounds__(NT, 2)
void k_selfq(int Ntot)
{
    extern __shared__ char smx[];
    half* sA = (half*)smx;
    half* sW = sA + 64 * LDH;
    const int tid = threadIdx.x;
    const int n0 = blockIdx.x * 64;
    const int rv = min(64, Ntot - n0);
#pragma unroll
    for (int j = 0; j < 4; j++) {
        int idx = tid + j * NT;            // 1024 = 64 rows x 16 segs
        int r = idx >> 4;
        int seg = (idx & 15) << 3;
        if (r < rv) cpa16h(sA + r * LDH + seg, g_z + ((size_t)(n0 + r) * 20 + 19) * 128 + seg);
        else *(uint4*)(sA + r * LDH + seg) = make_uint4(0, 0, 0, 0);
    }
    CP_COMMIT();
    float acc[2][4][4];
    ACC_ZERO2(acc);
    gemmH(acc, sA, g_wbuf + W_QS, sW, tid);
    const int lane = tid & 31, w = tid >> 5;
    const int mg = w & 1, ng = w >> 1;
    const int qr = lane >> 2, qc = lane & 3;
#pragma unroll
    for (int mt = 0; mt < 2; mt++)
#pragma unroll
        for (int hh = 0; hh < 2; hh++) {
            int lr = (mg * 2 + mt) * 16 + qr + hh * 8;
            if (lr < rv)
#pragma unroll
                for (int nt = 0; nt < 4; nt++) {
                    int cc = ng * 32 + nt * 8 + qc * 2;
                    size_t go = ((size_t)(n0 + lr) * 20 + 19) * 128 + cc;
                    half2 v = __floats2half2_rn(acc[mt][nt][hh * 2], acc[mt][nt][hh * 2 + 1]);
                    *(half2*)(g_q + go) = v;
                    *(half2*)(g_k + go) = v;
                    *(half2*)(g_v + go) = v;
                }
        }
}

// -------- kernel 3: attention + attn_fc + LN + FFN + LN + fuse + out --------
__global__ __launch_bounds__(NT, 2)
void k_anf(const float* __restrict__ afc_b, const float* __restrict__ aln_g,
           const float* __restrict__ aln_b,
           const float* __restrict__ f_b1, const float* __restrict__ f_b2,
           const float* __restrict__ fln_g, const float* __restrict__ fln_b,
           const float* __restrict__ f2n_w, const float* __restrict__ f2n_b,
           const float* __restrict__ oln_g, const float* __restrict__ oln_b,
           const float* __restrict__ nh, float* __restrict__ out, int Ntot)
{
    extern __shared__ char smx[];
    half*  sKh = (half*)smx;                 // K tile -> O -> X (64*LDH)
    half*  sVh = sKh + 64 * LDH;             // V tile -> H      (64*LDH)
    float* sP  = (float*)(sVh + 64 * LDH);   // fp32 scratch 64*LDA
    half*  sW  = (half*)(sP + 64 * LDA);     // 2*WCHH
    float* scr = (float*)(sW + 2 * WCHH);    // 1024 floats
    const int tid = threadIdx.x;
    const int nb0 = blockIdx.x * 3;
    const int nodes_here = min(3, Ntot - nb0);
    const int rows = nodes_here * 20;
    const size_t gbase = (size_t)nb0 * 20 * 128;

    // ---- stage K/V (half), zero pad rows ----
#pragma unroll
    for (int j = 0; j < 4; j++) {
        int idx = tid + j * NT;              // 1024 = 64 rows x 16 segs
        int r = idx >> 4;
        int seg = (idx & 15) << 3;
        if (r < rows) {
            cpa16h(sKh + r * LDH + seg, g_k + gbase + (size_t)r * 128 + seg);
            cpa16h(sVh + r * LDH + seg, g_v + gbase + (size_t)r * 128 + seg);
        } else {
            *(uint4*)(sKh + r * LDH + seg) = make_uint4(0, 0, 0, 0);
            *(uint4*)(sVh + r * LDH + seg) = make_uint4(0, 0, 0, 0);
        }
    }
    CP_COMMIT();
    CP_WAIT(0);
    __syncthreads();

    // ---- attention: thread owns (node, h, qi) ----
    const int node = tid / 80, h = (tid / 20) % 4, qi = tid % 20;
    const bool active = tid < nodes_here * 80;
    float oacc[32];
    if (active) {
        float qf[32];
        const half* qp = g_q + gbase + (size_t)(node * 20 + qi) * 128 + h * 32;
#pragma unroll
        for (int j = 0; j < 16; j++) {
            float2 f = __half22float2(*(const half2*)(qp + 2 * j));
            qf[2 * j] = f.x; qf[2 * j + 1] = f.y;
        }
        float p[20];
#pragma unroll
        for (int ki = 0; ki < 20; ki++) {
            const half* kp = sKh + (node * 20 + ki) * LDH + h * 32;
            float s = 0.f;
#pragma unroll
            for (int j = 0; j < 16; j++) {
                float2 kv = __half22float2(*(const half2*)(kp + 2 * j));
                s += qf[2 * j] * kv.x + qf[2 * j + 1] * kv.y;
            }
            p[ki] = s * 0.17677669529663687f;
        }
        float m = p[0];
#pragma unroll
        for (int ki = 1; ki < 20; ki++) m = fmaxf(m, p[ki]);
        float ssum = 0.f;
#pragma unroll
        for (int ki = 0; ki < 20; ki++) { p[ki] = expf(p[ki] - m); ssum += p[ki]; }
        float inv = 1.f / ssum;
#pragma unroll
        for (int j = 0; j < 32; j++) oacc[j] = 0.f;
#pragma unroll
        for (int ki = 0; ki < 20; ki++) {
            float pw = p[ki] * inv;
            const half* vp = sVh + (node * 20 + ki) * LDH + h * 32;
#pragma unroll
            for (int j = 0; j < 16; j++) {
                float2 vv = __half22float2(*(const half2*)(vp + 2 * j));
                oacc[2 * j]     += pw * vv.x;
                oacc[2 * j + 1] += pw * vv.y;
            }
        }
    }
    __syncthreads();   // all K/V reads done

    // O -> sKh (rows<60; pad rows remain zero)
    if (active) {
        half* op = sKh + (node * 20 + qi) * LDH + h * 32;
#pragma unroll
        for (int j = 0; j < 16; j++)
            *(half2*)(op + 2 * j) = __floats2half2_rn(oacc[2 * j], oacc[2 * j + 1]);
    }
    // first sync in gemm orders these writes

    // ---- attn_fc GEMM ----
    float acc[2][4][4];
    ACC_ZERO2(acc);
    gemmH(acc, sKh, g_wbuf + W_AFC, sW, tid);

    const int lane = tid & 31, w = tid >> 5;
    const int mg = w & 1, ng = w >> 1;
    const int qr = lane >> 2, qc = lane & 3;
#pragma unroll
    for (int mt = 0; mt < 2; mt++)
#pragma unroll
        for (int hh = 0; hh < 2; hh++) {
            int r = (mg * 2 + mt) * 16 + qr + hh * 8;
#pragma unroll
            for (int nt = 0; nt < 4; nt++) {
                int c = ng * 32 + nt * 8 + qc * 2;
                sP[r * LDA + c]     = acc[mt][nt][hh * 2];
                sP[r * LDA + c + 1] = acc[mt][nt][hh * 2 + 1];
            }
        }
    __syncthreads();

    // + afc_b + z residual
    for (int i = tid; i < 64 * 128; i += NT) {
        int r = i >> 7, d = i & 127;
        if (r < rows)
            sP[r * LDA + d] += afc_b[d] + __half2float(g_z[gbase + (size_t)r * 128 + d]);
    }
    __syncthreads();

    // ---- attn LN -> X (half, into sKh; pad rows of sKh stay zero) ----
    if (tid < rows) {
        float m = 0.f;
#pragma unroll 8
        for (int dd = 0; dd < 128; dd++) m += sP[tid * LDA + ((dd + tid) & 127)];
        m *= (1.0f / 128.0f);
        float v = 0.f;
#pragma unroll 8
        for (int dd = 0; dd < 128; dd++) { float x = sP[tid * LDA + ((dd + tid) & 127)] - m; v += x * x; }
        v *= (1.0f / 128.0f);
        scr[tid] = m;
        scr[64 + tid] = rsqrtf(v + 1e-5f);
    }
    __syncthreads();
    for (int i = tid; i < rows * 128; i += NT) {
        int r = i >> 7, d = i & 127;
        float y = (sP[r * LDA + d] - scr[r]) * scr[64 + r] * aln_g[d] + aln_b[d];
        sKh[r * LDH + d] = __float2half_rn(y);
    }
    __syncthreads();

    // ---- FFN: 4 column chunks, x2 accumulated in registers ----
    float x2[2][4][4];
    ACC_ZERO2(x2);
    for (int c = 0; c < 4; c++) {
        ACC_ZERO2(acc);
        gemmH(acc, sKh, g_wbuf + W_F1 + c * 16384, sW, tid);
#pragma unroll
        for (int mt = 0; mt < 2; mt++)
#pragma unroll
            for (int hh = 0; hh < 2; hh++) {
                int r = (mg * 2 + mt) * 16 + qr + hh * 8;
#pragma unroll
                for (int nt = 0; nt < 4; nt++) {
                    int col = ng * 32 + nt * 8 + qc * 2;
                    float b0 = f_b1[c * 128 + col], b1 = f_b1[c * 128 + col + 1];
                    *(half2*)(sVh + r * LDH + col) = __floats2half2_rn(
                        fmaxf(acc[mt][nt][hh * 2] + b0, 0.f),
                        fmaxf(acc[mt][nt][hh * 2 + 1] + b1, 0.f));
                }
            }
        __syncthreads();
        gemmH(x2, sVh, g_wbuf + W_F2 + c * 16384, sW, tid);
    }

    // x2 + b2 + X -> sP
#pragma unroll
    for (int mt = 0; mt < 2; mt++)
#pragma unroll
        for (int hh = 0; hh < 2; hh++) {
            int r = (mg * 2 + mt) * 16 + qr + hh * 8;
#pragma unroll
            for (int nt = 0; nt < 4; nt++) {
                int col = ng * 32 + nt * 8 + qc * 2;
                float2 xv = __half22float2(*(const half2*)(sKh + r * LDH + col));
                sP[r * LDA + col]     = x2[mt][nt][hh * 2]     + f_b2[col]     + xv.x;
                sP[r * LDA + col + 1] = x2[mt][nt][hh * 2 + 1] + f_b2[col + 1] + xv.y;
            }
        }
    __syncthreads();

    // ---- FFN LN (in place in sP) ----
    if (tid < rows) {
        float m = 0.f;
#pragma unroll 8
        for (int dd = 0; dd < 128; dd++) m += sP[tid * LDA + ((dd + tid) & 127)];
        m *= (1.0f / 128.0f);
        float v = 0.f;
#pragma unroll 8
        for (int dd = 0; dd < 128; dd++) { float x = sP[tid * LDA + ((dd + tid) & 127)] - m; v += x * x; }
        v *= (1.0f / 128.0f);
        scr[tid] = m;
        scr[64 + tid] = rsqrtf(v + 1e-5f);
    }
    __syncthreads();
    for (int i = tid; i < rows * 128; i += NT) {
        int r = i >> 7, d = i & 127;
        sP[r * LDA + d] = (sP[r * LDA + d] - scr[r]) * scr[64 + r] * fln_g[d] + fln_b[d];
    }
    __syncthreads();

    // ---- fuse: neighborhood mean, fea2node, out LN ----
    float* sNe = scr + 128;
    float* sY  = scr + 512;
    for (int i = tid; i < nodes_here * 128; i += NT) {
        int nn = i >> 7, d = i & 127;
        float s = 0.f;
#pragma unroll
        for (int k = 0; k < 19; k++) s += sP[(nn * 20 + k) * LDA + d];
        sNe[i] = s * (1.0f / 19.0f);
    }
    __syncthreads();
    for (int idx = tid; idx < nodes_here * 128; idx += NT) {
        int nn = idx >> 7, d = idx & 127;
        const float* selfr = sP + (nn * 20 + 19) * LDA;
        const float* ne = sNe + nn * 128;
        float a = 0.f;
#pragma unroll 4
        for (int e = 0; e < 128; e++) a += selfr[e] * f2n_w[e * 128 + d];
#pragma unroll 4
        for (int e = 0; e < 128; e++) a += ne[e] * f2n_w[(128 + e) * 128 + d];
        float y = gelu_exact(a + f2n_b[d])
                + nh[((size_t)(nb0 + nn) * 20 + 19) * 128 + d];
        sY[idx] = y;
    }
    __syncthreads();
    if (tid < nodes_here) {
        float m = 0.f;
        for (int d = 0; d < 128; d++) m += sY[tid * 128 + d];
        m *= (1.0f / 128.0f);
        float v = 0.f;
        for (int d = 0; d < 128; d++) { float x = sY[tid * 128 + d] - m; v += x * x; }
        v *= (1.0f / 128.0f);
        scr[896 + tid] = m;
        scr[900 + tid] = rsqrtf(v + 1e-5f);
    }
    __syncthreads();
    for (int idx = tid; idx < nodes_here * 128; idx += NT) {
        int nn = idx >> 7, d = idx & 127;
        float y = (sY[idx] - scr[896 + nn]) * scr[900 + nn];
        out[(size_t)(nb0 + nn) * 128 + d] = y * oln_g[d] + oln_b[d];
    }
}

// ------------------- launch -------------------
#define SM_ZQKV ((2 * 64 * LDH + 2 * WCHH) * 2)
#define SM_SQ   ((64 * LDH + 2 * WCHH) * 2)
#define SM_ANF  ((2 * 64 * LDH + 2 * WCHH) * 2 + 64 * LDA * 4 + 1024 * 4)

extern "C" void kernel_launch(void* const* d_in, const int* in_sizes, int n_in,
                              void* d_out, int out_size) {
    (void)n_in; (void)out_size;
    const float* nh      = (const float*)d_in[0];
    const float* t       = (const float*)d_in[1];
    const float* t_now   = (const float*)d_in[2];
    const float* ef      = (const float*)d_in[3];
    const float* bfreq   = (const float*)d_in[4];
    const float* phase   = (const float*)d_in[5];
    const float* e_w     = (const float*)d_in[6];
    const float* e_b     = (const float*)d_in[7];
    const float* wq      = (const float*)d_in[8];
    const float* wk      = (const float*)d_in[9];
    const float* wv      = (const float*)d_in[10];
    const float* wq_src  = (const float*)d_in[11];
    const float* afc_w   = (const float*)d_in[12];
    const float* afc_b   = (const float*)d_in[13];
    const float* aln_g   = (const float*)d_in[14];
    const float* aln_b   = (const float*)d_in[15];
    const float* f_w1    = (const float*)d_in[16];
    const float* f_b1    = (const float*)d_in[17];
    const float* f_w2    = (const float*)d_in[18];
    const float* f_b2    = (const float*)d_in[19];
    const float* fln_g   = (const float*)d_in[20];
    const float* fln_b   = (const float*)d_in[21];
    const float* f2n_w   = (const float*)d_in[22];
    const float* f2n_b   = (const float*)d_in[23];
    const float* oln_g   = (const float*)d_in[24];
    const float* oln_b   = (const float*)d_in[25];
    float* out = (float*)d_out;

    const int N = in_sizes[0] / 2560;
    const long totrows = (long)N * 20;
    const int gM = (int)((totrows + 63) / 64);

    cudaFuncSetAttribute(k_zqkv,  cudaFuncAttributeMaxDynamicSharedMemorySize, SM_ZQKV);
    cudaFuncSetAttribute(k_selfq, cudaFuncAttributeMaxDynamicSharedMemorySize, SM_SQ);
    cudaFuncSetAttribute(k_anf,   cudaFuncAttributeMaxDynamicSharedMemorySize, SM_ANF);

    k_prep<<<(W_TOT + 255) / 256, 256>>>(e_w, wq, wk, wv, wq_src, afc_w, f_w1, f_w2);
    k_zqkv<<<gM, NT, SM_ZQKV>>>(nh, t, t_now, ef, bfreq, phase, e_b, totrows);
    k_selfq<<<(N + 63) / 64, NT, SM_SQ>>>(N);
    k_anf<<<(N + 2) / 3, NT, SM_ANF>>>(afc_b, aln_g, aln_b,
                                       f_b1, f_b2, fln_g, fln_b,
                                       f2n_w, f2n_b, oln_g, oln_b, nh, out, N);
}

// round 16
// speedup vs baseline: 1.4003x; 1.0011x over previous
#include <cuda_runtime.h>
#include <cuda_fp16.h>
#include <math.h>

#define LDH 136       // half stride for activation tiles
#define LDA 132       // fp32 scratch stride
#define NT 256
#define WCHH 4096     // halfs per packed 32-k weight chunk (8KB)
#define MAXROWS (20000*20)

__device__ half g_z[(size_t)MAXROWS*128];
__device__ half g_q[(size_t)MAXROWS*128];
__device__ half g_k[(size_t)MAXROWS*128];
__device__ half g_v[(size_t)MAXROWS*128];

// fragment-packed fp16 weights (element-count offsets)
#define W_EW  0
#define W_Q   16384
#define W_K   32768
#define W_V   49152
#define W_QS  65536
#define W_AFC 81920
#define W_F1  98304
#define W_F2  163840
#define W_TOT 229376
__device__ half g_wbuf[W_TOT];

__device__ __forceinline__ float gelu_exact(float x) {
    return 0.5f * x * (1.0f + erff(x * 0.7071067811865475f));
}

__device__ __forceinline__ void mma_f16(float d[4], const unsigned a[4], const unsigned b[2]) {
    asm volatile(
        "mma.sync.aligned.m16n8k16.row.col.f32.f16.f16.f32 "
        "{%0,%1,%2,%3}, {%4,%5,%6,%7}, {%8,%9}, {%0,%1,%2,%3};"
        : "+f"(d[0]), "+f"(d[1]), "+f"(d[2]), "+f"(d[3])
        : "r"(a[0]), "r"(a[1]), "r"(a[2]), "r"(a[3]), "r"(b[0]), "r"(b[1]));
}

__device__ __forceinline__ void ldsm4(unsigned a[4], const half* p) {
    unsigned addr = (unsigned)__cvta_generic_to_shared(p);
    asm volatile("ldmatrix.sync.aligned.m8n8.x4.shared.b16 {%0,%1,%2,%3}, [%4];"
        : "=r"(a[0]), "=r"(a[1]), "=r"(a[2]), "=r"(a[3]) : "r"(addr));
}

#define ACC_ZERO2(acc) do { _Pragma("unroll") for (int _m=0;_m<2;_m++) _Pragma("unroll") for (int _n=0;_n<4;_n++) { acc[_m][_n][0]=0.f;acc[_m][_n][1]=0.f;acc[_m][_n][2]=0.f;acc[_m][_n][3]=0.f; } } while(0)

__device__ __forceinline__ void cpa16h(half* dst, const half* src) {
    unsigned u = (unsigned)__cvta_generic_to_shared(dst);
    asm volatile("cp.async.cg.shared.global [%0], [%1], 16;\n" :: "r"(u), "l"(src));
}
#define CP_COMMIT() asm volatile("cp.async.commit_group;\n")
#define CP_WAIT(n)  asm volatile("cp.async.wait_group %0;\n" :: "n"(n))

// stage one packed 32-k chunk (4096 halfs = 8KB, contiguous)
__device__ __forceinline__ void stageWh(half* dst, const half* __restrict__ W,
                                        int kc, int tid) {
#pragma unroll
    for (int j = 0; j < 2; j++) {
        int idx = (tid + j * NT) << 3;       // 8 halfs = 16B per op, 512 ops
        cpa16h(dst + idx, W + kc * WCHH + idx);
    }
}

// M=64 fp16 GEMM on fragment-packed weights: acc[2][4][4] fp32, warp grid 2(M)x4(N)
// 3-stage weight ring, ONE sync per k-chunk + trailing sync. ldmatrix A loads.
__device__ __forceinline__ void gemmH(float acc[2][4][4], const half* actH,
                                      const half* __restrict__ Wg,
                                      half* sWbuf, int tid) {
    const int lane = tid & 31, w = tid >> 5;
    const int mg = w & 1, ng = w >> 1;
    const int g = lane >> 2, t = lane & 3;
    const int arow = lane & 15, acol = (lane >> 4) << 3;
    stageWh(sWbuf, Wg, 0, tid);
    CP_COMMIT();
#pragma unroll
    for (int kc = 0; kc < 4; kc++) {
        if (kc < 3) {
            stageWh(sWbuf + ((kc + 1) % 3) * WCHH, Wg, kc + 1, tid);
            CP_COMMIT();
            CP_WAIT(1);
        } else {
            CP_WAIT(0);
        }
        __syncthreads();
        const half* sw = sWbuf + (kc % 3) * WCHH;
#pragma unroll
        for (int ks2 = 0; ks2 < 2; ks2++) {
            unsigned bb[4][2];
#pragma unroll
            for (int nt = 0; nt < 4; nt++) {
                int n = ng * 32 + nt * 8 + g;
                uint2 bv = *(const uint2*)(sw + ks2 * 2048 + n * 16 + t * 4);
                bb[nt][0] = bv.x; bb[nt][1] = bv.y;
            }
            const int k0 = kc * 32 + ks2 * 16;
#pragma unroll
            for (int mt = 0; mt < 2; mt++) {
                unsigned a4[4];
                ldsm4(a4, actH + ((mg * 2 + mt) * 16 + arow) * LDH + k0 + acol);
#pragma unroll
                for (int nt = 0; nt < 4; nt++) mma_f16(acc[mt][nt], a4, bb[nt]);
            }
        }
    }
    __syncthreads();   // protect weight ring + activation buffers for caller
}

// ------------------- kernel 0: pack weights to fp16 fragment order ----------
// per 128x128 matrix: 4 chunks of 4096 halfs; within chunk: [ks2][n][t][e],
// k = kc*32 + ks2*16 + 2t + (e&1) + 8*(e>>1)
__global__ void k_prep(const float* __restrict__ e_w, const float* __restrict__ wq,
                       const float* __restrict__ wk, const float* __restrict__ wv,
                       const float* __restrict__ wq_src, const float* __restrict__ afc_w,
                       const float* __restrict__ f_w1, const float* __restrict__ f_w2)
{
    int i = blockIdx.x * 256 + threadIdx.x;
    if (i >= W_TOT) return;
    const float* src; int rel; int ldw = 128; int kbase = 0; int nbase = 0;
    if      (i < W_Q)   { src = e_w;    rel = i - W_EW; }
    else if (i < W_K)   { src = wq;     rel = i - W_Q; }
    else if (i < W_V)   { src = wk;     rel = i - W_K; }
    else if (i < W_QS)  { src = wv;     rel = i - W_V; }
    else if (i < W_AFC) { src = wq_src; rel = i - W_QS; }
    else if (i < W_F1)  { src = afc_w;  rel = i - W_AFC; }
    else if (i < W_F2)  { src = f_w1;   rel = i - W_F1;
                          int c = rel / 16384; rel -= c * 16384; ldw = 512; nbase = c * 128; }
    else                { src = f_w2;   rel = i - W_F2;
                          int c = rel / 16384; rel -= c * 16384; kbase = c * 128; }
    int kc = rel >> 12;
    int within = rel & 4095;
    int ks2 = within >> 11;
    int remn = within & 2047;
    int n = remn >> 4;
    int rem2 = remn & 15;
    int t = rem2 >> 2;
    int e = rem2 & 3;
    int k = kc * 32 + ks2 * 16 + 2 * t + (e & 1) + 8 * (e >> 1);
    g_wbuf[i] = __float2half_rn(src[(size_t)(kbase + k) * ldw + nbase + n]);
}

// ------------------- kernel 1: z + qkv fused -------------------
__global__ __launch_bounds__(NT, 2)
void k_zqkv(const float* __restrict__ nh, const float* __restrict__ t,
            const float* __restrict__ t_now, const float* __restrict__ ef,
            const float* __restrict__ bfreq, const float* __restrict__ phase,
            const float* __restrict__ e_b, long totrows)
{
    extern __shared__ char smx[];
    half* sA = (half*)smx;                 // 64*LDH
    half* sZ = sA + 64 * LDH;              // 64*LDH
    half* sW = sZ + 64 * LDH;              // 3*WCHH
    const int tid = threadIdx.x;
    const long row0 = (long)blockIdx.x * 64;
    const int rv = (int)min((long)64, totrows - row0);

    // stage ef (fp32 -> half)
#pragma unroll
    for (int j = 0; j < 8; j++) {
        int idx = tid + j * NT;            // 2048 = 64 rows x 32 segs
        int r = idx >> 5;
        int c4 = (idx & 31) << 2;
        float4 v = make_float4(0.f, 0.f, 0.f, 0.f);
        if (r < rv) v = *(const float4*)(ef + (size_t)(row0 + r) * 128 + c4);
        half2* dp = (half2*)(sA + r * LDH + c4);
        dp[0] = __floats2half2_rn(v.x, v.y);
        dp[1] = __floats2half2_rn(v.z, v.w);
    }
    __syncthreads();

    float acc[2][4][4];
    ACC_ZERO2(acc);
    gemmH(acc, sA, g_wbuf + W_EW, sW, tid);

    const float tn = t_now[0];
    const int lane = tid & 31, w = tid >> 5;
    const int mg = w & 1, ng = w >> 1;
    const int qr = lane >> 2, qc = lane & 3;
#pragma unroll
    for (int mt = 0; mt < 2; mt++) {
#pragma unroll
        for (int hh = 0; hh < 2; hh++) {
            int lr = (mg * 2 + mt) * 16 + qr + hh * 8;
            long gr = row0 + lr;
            bool ok = (lr < rv);
            float tv = ok ? t[gr] : 0.f;
#pragma unroll
            for (int nt = 0; nt < 4; nt++) {
                int cc = ng * 32 + nt * 8 + qc * 2;
                float zv0 = 0.f, zv1 = 0.f;
                if (ok) {
                    float g0 = gelu_exact(acc[mt][nt][hh * 2] + e_b[cc]);
                    float g1 = gelu_exact(acc[mt][nt][hh * 2 + 1] + e_b[cc + 1]);
                    zv0 = nh[(size_t)gr * 128 + cc] + g0 + cosf((tn - tv) * bfreq[cc] + phase[cc]);
                    zv1 = nh[(size_t)gr * 128 + cc + 1] + g1 + cosf((tn - tv) * bfreq[cc + 1] + phase[cc + 1]);
                }
                half2 hz = __floats2half2_rn(zv0, zv1);
                if (ok) *(half2*)(g_z + (size_t)gr * 128 + cc) = hz;
                *(half2*)(sZ + lr * LDH + cc) = hz;
            }
        }
    }
    __syncthreads();

#pragma unroll
    for (int which = 0; which < 3; which++) {
        const half* Wg = (which == 0) ? g_wbuf + W_Q : (which == 1) ? g_wbuf + W_K : g_wbuf + W_V;
        half* dst = (which == 0) ? g_q : (which == 1) ? g_k : g_v;
        ACC_ZERO2(acc);
        gemmH(acc, sZ, Wg, sW, tid);
#pragma unroll
        for (int mt = 0; mt < 2; mt++)
#pragma unroll
            for (int hh = 0; hh < 2; hh++) {
                int lr = (mg * 2 + mt) * 16 + qr + hh * 8;
                if (lr < rv)
#pragma unroll
                    for (int nt = 0; nt < 4; nt++) {
                        int cc = ng * 32 + nt * 8 + qc * 2;
                        *(half2*)(dst + (size_t)(row0 + lr) * 128 + cc) =
                            __floats2half2_rn(acc[mt][nt][hh * 2], acc[mt][nt][hh * 2 + 1]);
                    }
            }
    }
}

// ------------------- kernel 2: self_q -------------------
__global__ __launch_bounds__(NT, 2)
void k_selfq(int Ntot)
{
    extern __shared__ char smx[];
    half* sA = (half*)smx;
    half* sW = sA + 64 * LDH;
    const int tid = threadIdx.x;
    const int n0 = blockIdx.x * 64;
    const int rv = min(64, Ntot - n0);
#pragma unroll
    for (int j = 0; j < 4; j++) {
        int idx = tid + j * NT;            // 1024 = 64 rows x 16 segs
        int r = idx >> 4;
        int seg = (idx & 15) << 3;
        if (r < rv) cpa16h(sA + r * LDH + seg, g_z + ((size_t)(n0 + r) * 20 + 19) * 128 + seg);
        else *(uint4*)(sA + r * LDH + seg) = make_uint4(0, 0, 0, 0);
    }
    CP_COMMIT();
    float acc[2][4][4];
    ACC_ZERO2(acc);
    gemmH(acc, sA, g_wbuf + W_QS, sW, tid);
    const int lane = tid & 31, w = tid >> 5;
    const int mg = w & 1, ng = w >> 1;
    const int qr = lane >> 2, qc = lane & 3;
#pragma unroll
    for (int mt = 0; mt < 2; mt++)
#pragma unroll
        for (int hh = 0; hh < 2; hh++) {
            int lr = (mg * 2 + mt) * 16 + qr + hh * 8;
            if (lr < rv)
#pragma unroll
                for (int nt = 0; nt < 4; nt++) {
                    int cc = ng * 32 + nt * 8 + qc * 2;
                    size_t go = ((size_t)(n0 + lr) * 20 + 19) * 128 + cc;
                    half2 v = __floats2half2_rn(acc[mt][nt][hh * 2], acc[mt][nt][hh * 2 + 1]);
                    *(half2*)(g_q + go) = v;
                    *(half2*)(g_k + go) = v;
                    *(half2*)(g_v + go) = v;
                }
        }
}

// -------- kernel 3: attention + attn_fc + LN + FFN + LN + fuse + out --------
__global__ __launch_bounds__(NT, 2)
void k_anf(const float* __restrict__ afc_b, const float* __restrict__ aln_g,
           const float* __restrict__ aln_b,
           const float* __restrict__ f_b1, const float* __restrict__ f_b2,
           const float* __restrict__ fln_g, const float* __restrict__ fln_b,
           const float* __restrict__ f2n_w, const float* __restrict__ f2n_b,
           const float* __restrict__ oln_g, const float* __restrict__ oln_b,
           const float* __restrict__ nh, float* __restrict__ out, int Ntot)
{
    extern __shared__ char smx[];
    half*  sKh = (half*)smx;                 // K tile -> O -> X (64*LDH)
    half*  sVh = sKh + 64 * LDH;             // V tile -> H      (64*LDH)
    float* sP  = (float*)(sVh + 64 * LDH);   // fp32 scratch 64*LDA
    half*  sW  = (half*)(sP + 64 * LDA);     // 3*WCHH
    float* scr = (float*)(sW + 3 * WCHH);    // 1024 floats
    const int tid = threadIdx.x;
    const int nb0 = blockIdx.x * 3;
    const int nodes_here = min(3, Ntot - nb0);
    const int rows = nodes_here * 20;
    const size_t gbase = (size_t)nb0 * 20 * 128;

    // ---- stage K/V (half), zero pad rows ----
#pragma unroll
    for (int j = 0; j < 4; j++) {
        int idx = tid + j * NT;              // 1024 = 64 rows x 16 segs
        int r = idx >> 4;
        int seg = (idx & 15) << 3;
        if (r < rows) {
            cpa16h(sKh + r * LDH + seg, g_k + gbase + (size_t)r * 128 + seg);
            cpa16h(sVh + r * LDH + seg, g_v + gbase + (size_t)r * 128 + seg);
        } else {
            *(uint4*)(sKh + r * LDH + seg) = make_uint4(0, 0, 0, 0);
            *(uint4*)(sVh + r * LDH + seg) = make_uint4(0, 0, 0, 0);
        }
    }
    CP_COMMIT();
    CP_WAIT(0);
    __syncthreads();

    // ---- attention: thread owns (node, h, qi) ----
    const int node = tid / 80, h = (tid / 20) % 4, qi = tid % 20;
    const bool active = tid < nodes_here * 80;
    float oacc[32];
    if (active) {
        float qf[32];
        const half* qp = g_q + gbase + (size_t)(node * 20 + qi) * 128 + h * 32;
#pragma unroll
        for (int j = 0; j < 16; j++) {
            float2 f = __half22float2(*(const half2*)(qp + 2 * j));
            qf[2 * j] = f.x; qf[2 * j + 1] = f.y;
        }
        float p[20];
#pragma unroll
        for (int ki = 0; ki < 20; ki++) {
            const half* kp = sKh + (node * 20 + ki) * LDH + h * 32;
            float s = 0.f;
#pragma unroll
            for (int j = 0; j < 16; j++) {
                float2 kv = __half22float2(*(const half2*)(kp + 2 * j));
                s += qf[2 * j] * kv.x + qf[2 * j + 1] * kv.y;
            }
            p[ki] = s * 0.17677669529663687f;
        }
        float m = p[0];
#pragma unroll
        for (int ki = 1; ki < 20; ki++) m = fmaxf(m, p[ki]);
        float ssum = 0.f;
#pragma unroll
        for (int ki = 0; ki < 20; ki++) { p[ki] = expf(p[ki] - m); ssum += p[ki]; }
        float inv = 1.f / ssum;
#pragma unroll
        for (int j = 0; j < 32; j++) oacc[j] = 0.f;
#pragma unroll
        for (int ki = 0; ki < 20; ki++) {
            float pw = p[ki] * inv;
            const half* vp = sVh + (node * 20 + ki) * LDH + h * 32;
#pragma unroll
            for (int j = 0; j < 16; j++) {
                float2 vv = __half22float2(*(const half2*)(vp + 2 * j));
                oacc[2 * j]     += pw * vv.x;
                oacc[2 * j + 1] += pw * vv.y;
            }
        }
    }
    __syncthreads();   // all K/V reads done

    // O -> sKh (rows<60; pad rows remain zero)
    if (active) {
        half* op = sKh + (node * 20 + qi) * LDH + h * 32;
#pragma unroll
        for (int j = 0; j < 16; j++)
            *(half2*)(op + 2 * j) = __floats2half2_rn(oacc[2 * j], oacc[2 * j + 1]);
    }
    // first sync in gemm orders these writes

    // ---- attn_fc GEMM ----
    float acc[2][4][4];
    ACC_ZERO2(acc);
    gemmH(acc, sKh, g_wbuf + W_AFC, sW, tid);

    const int lane = tid & 31, w = tid >> 5;
    const int mg = w & 1, ng = w >> 1;
    const int qr = lane >> 2, qc = lane & 3;
#pragma unroll
    for (int mt = 0; mt < 2; mt++)
#pragma unroll
        for (int hh = 0; hh < 2; hh++) {
            int r = (mg * 2 + mt) * 16 + qr + hh * 8;
#pragma unroll
            for (int nt = 0; nt < 4; nt++) {
                int c = ng * 32 + nt * 8 + qc * 2;
                sP[r * LDA + c]     = acc[mt][nt][hh * 2];
                sP[r * LDA + c + 1] = acc[mt][nt][hh * 2 + 1];
            }
        }
    __syncthreads();

    // + afc_b + z residual
    for (int i = tid; i < 64 * 128; i += NT) {
        int r = i >> 7, d = i & 127;
        if (r < rows)
            sP[r * LDA + d] += afc_b[d] + __half2float(g_z[gbase + (size_t)r * 128 + d]);
    }
    __syncthreads();

    // ---- attn LN -> X (half, into sKh; pad rows of sKh stay zero) ----
    if (tid < rows) {
        float m = 0.f;
#pragma unroll 8
        for (int dd = 0; dd < 128; dd++) m += sP[tid * LDA + ((dd + tid) & 127)];
        m *= (1.0f / 128.0f);
        float v = 0.f;
#pragma unroll 8
        for (int dd = 0; dd < 128; dd++) { float x = sP[tid * LDA + ((dd + tid) & 127)] - m; v += x * x; }
        v *= (1.0f / 128.0f);
        scr[tid] = m;
        scr[64 + tid] = rsqrtf(v + 1e-5f);
    }
    __syncthreads();
    for (int i = tid; i < rows * 128; i += NT) {
        int r = i >> 7, d = i & 127;
        float y = (sP[r * LDA + d] - scr[r]) * scr[64 + r] * aln_g[d] + aln_b[d];
        sKh[r * LDH + d] = __float2half_rn(y);
    }
    __syncthreads();

    // ---- FFN: 4 column chunks, x2 accumulated in registers ----
    float x2[2][4][4];
    ACC_ZERO2(x2);
    for (int c = 0; c < 4; c++) {
        ACC_ZERO2(acc);
        gemmH(acc, sKh, g_wbuf + W_F1 + c * 16384, sW, tid);
#pragma unroll
        for (int mt = 0; mt < 2; mt++)
#pragma unroll
            for (int hh = 0; hh < 2; hh++) {
                int r = (mg * 2 + mt) * 16 + qr + hh * 8;
#pragma unroll
                for (int nt = 0; nt < 4; nt++) {
                    int col = ng * 32 + nt * 8 + qc * 2;
                    float b0 = f_b1[c * 128 + col], b1 = f_b1[c * 128 + col + 1];
                    *(half2*)(sVh + r * LDH + col) = __floats2half2_rn(
                        fmaxf(acc[mt][nt][hh * 2] + b0, 0.f),
                        fmaxf(acc[mt][nt][hh * 2 + 1] + b1, 0.f));
                }
            }
        __syncthreads();
        gemmH(x2, sVh, g_wbuf + W_F2 + c * 16384, sW, tid);
    }

    // x2 + b2 + X -> sP
#pragma unroll
    for (int mt = 0; mt < 2; mt++)
#pragma unroll
        for (int hh = 0; hh < 2; hh++) {
            int r = (mg * 2 + mt) * 16 + qr + hh * 8;
#pragma unroll
            for (int nt = 0; nt < 4; nt++) {
                int col = ng * 32 + nt * 8 + qc * 2;
                float2 xv = __half22float2(*(const half2*)(sKh + r * LDH + col));
                sP[r * LDA + col]     = x2[mt][nt][hh * 2]     + f_b2[col]     + xv.x;
                sP[r * LDA + col + 1] = x2[mt][nt][hh * 2 + 1] + f_b2[col + 1] + xv.y;
            }
        }
    __syncthreads();

    // ---- FFN LN (in place in sP) ----
    if (tid < rows) {
        float m = 0.f;
#pragma unroll 8
        for (int dd = 0; dd < 128; dd++) m += sP[tid * LDA + ((dd + tid) & 127)];
        m *= (1.0f / 128.0f);
        float v = 0.f;
#pragma unroll 8
        for (int dd = 0; dd < 128; dd++) { float x = sP[tid * LDA + ((dd + tid) & 127)] - m; v += x * x; }
        v *= (1.0f / 128.0f);
        scr[tid] = m;
        scr[64 + tid] = rsqrtf(v + 1e-5f);
    }
    __syncthreads();
    for (int i = tid; i < rows * 128; i += NT) {
        int r = i >> 7, d = i & 127;
        sP[r * LDA + d] = (sP[r * LDA + d] - scr[r]) * scr[64 + r] * fln_g[d] + fln_b[d];
    }
    __syncthreads();

    // ---- fuse: neighborhood mean, fea2node, out LN ----
    float* sNe = scr + 128;
    float* sY  = scr + 512;
    for (int i = tid; i < nodes_here * 128; i += NT) {
        int nn = i >> 7, d = i & 127;
        float s = 0.f;
#pragma unroll
        for (int k = 0; k < 19; k++) s += sP[(nn * 20 + k) * LDA + d];
        sNe[i] = s * (1.0f / 19.0f);
    }
    __syncthreads();
    for (int idx = tid; idx < nodes_here * 128; idx += NT) {
        int nn = idx >> 7, d = idx & 127;
        const float* selfr = sP + (nn * 20 + 19) * LDA;
        const float* ne = sNe + nn * 128;
        float a = 0.f;
#pragma unroll 4
        for (int e = 0; e < 128; e++) a += selfr[e] * f2n_w[e * 128 + d];
#pragma unroll 4
        for (int e = 0; e < 128; e++) a += ne[e] * f2n_w[(128 + e) * 128 + d];
        float y = gelu_exact(a + f2n_b[d])
                + nh[((size_t)(nb0 + nn) * 20 + 19) * 128 + d];
        sY[idx] = y;
    }
    __syncthreads();
    if (tid < nodes_here) {
        float m = 0.f;
        for (int d = 0; d < 128; d++) m += sY[tid * 128 + d];
        m *= (1.0f / 128.0f);
        float v = 0.f;
        for (int d = 0; d < 128; d++) { float x = sY[tid * 128 + d] - m; v += x * x; }
        v *= (1.0f / 128.0f);
        scr[896 + tid] = m;
        scr[900 + tid] = rsqrtf(v + 1e-5f);
    }
    __syncthreads();
    for (int idx = tid; idx < nodes_here * 128; idx += NT) {
        int nn = idx >> 7, d = idx & 127;
        float y = (sY[idx] - scr[896 + nn]) * scr[900 + nn];
        out[(size_t)(nb0 + nn) * 128 + d] = y * oln_g[d] + oln_b[d];
    }
}

// ------------------- launch -------------------
#define SM_ZQKV ((2 * 64 * LDH + 3 * WCHH) * 2)
#define SM_SQ   ((64 * LDH + 3 * WCHH) * 2)
#define SM_ANF  ((2 * 64 * LDH + 3 * WCHH) * 2 + 64 * LDA * 4 + 1024 * 4)

extern "C" void kernel_launch(void* const* d_in, const int* in_sizes, int n_in,
                              void* d_out, int out_size) {
    (void)n_in; (void)out_size;
    const float* nh      = (const float*)d_in[0];
    const float* t       = (const float*)d_in[1];
    const float* t_now   = (const float*)d_in[2];
    const float* ef      = (const float*)d_in[3];
    const float* bfreq   = (const float*)d_in[4];
    const float* phase   = (const float*)d_in[5];
    const float* e_w     = (const float*)d_in[6];
    const float* e_b     = (const float*)d_in[7];
    const float* wq      = (const float*)d_in[8];
    const float* wk      = (const float*)d_in[9];
    const float* wv      = (const float*)d_in[10];
    const float* wq_src  = (const float*)d_in[11];
    const float* afc_w   = (const float*)d_in[12];
    const float* afc_b   = (const float*)d_in[13];
    const float* aln_g   = (const float*)d_in[14];
    const float* aln_b   = (const float*)d_in[15];
    const float* f_w1    = (const float*)d_in[16];
    const float* f_b1    = (const float*)d_in[17];
    const float* f_w2    = (const float*)d_in[18];
    const float* f_b2    = (const float*)d_in[19];
    const float* fln_g   = (const float*)d_in[20];
    const float* fln_b   = (const float*)d_in[21];
    const float* f2n_w   = (const float*)d_in[22];
    const float* f2n_b   = (const float*)d_in[23];
    const float* oln_g   = (const float*)d_in[24];
    const float* oln_b   = (const float*)d_in[25];
    float* out = (float*)d_out;

    const int N = in_sizes[0] / 2560;
    const long totrows = (long)N * 20;
    const int gM = (int)((totrows + 63) / 64);

    cudaFuncSetAttribute(k_zqkv,  cudaFuncAttributeMaxDynamicSharedMemorySize, SM_ZQKV);
    cudaFuncSetAttribute(k_selfq, cudaFuncAttributeMaxDynamicSharedMemorySize, SM_SQ);
    cudaFuncSetAttribute(k_anf,   cudaFuncAttributeMaxDynamicSharedMemorySize, SM_ANF);

    k_prep<<<(W_TOT + 255) / 256, 256>>>(e_w, wq, wk, wv, wq_src, afc_w, f_w1, f_w2);
    k_zqkv<<<gM, NT, SM_ZQKV>>>(nh, t, t_now, ef, bfreq, phase, e_b, totrows);
    k_selfq<<<(N + 63) / 64, NT, SM_SQ>>>(N);
    k_anf<<<(N + 2) / 3, NT, SM_ANF>>>(afc_b, aln_g, aln_b,
                                       f_b1, f_b2, fln_g, fln_b,
                                       f2n_w, f2n_b, oln_g, oln_b, nh, out, N);
}

// round 17
// speedup vs baseline: 1.4385x; 1.0273x over previous
#include <cuda_runtime.h>
#include <cuda_fp16.h>
#include <math.h>

#define LDH 136       // half stride for activation tiles
#define LDAX 132      // fp32 X stride
#define NT 256
#define WCHH 4096     // halfs per packed 32-k weight chunk (8KB)

// fragment-packed fp16 weights (element-count offsets)
#define W_EW  0
#define W_Q   16384
#define W_K   32768
#define W_V   49152
#define W_QS  65536
#define W_AFC 81920
#define W_F1  98304
#define W_F2  163840
#define W_TOT 229376
__device__ half g_wbuf[W_TOT];

__device__ __forceinline__ float gelu_exact(float x) {
    return 0.5f * x * (1.0f + erff(x * 0.7071067811865475f));
}

__device__ __forceinline__ void mma_f16(float d[4], const unsigned a[4], const unsigned b[2]) {
    asm volatile(
        "mma.sync.aligned.m16n8k16.row.col.f32.f16.f16.f32 "
        "{%0,%1,%2,%3}, {%4,%5,%6,%7}, {%8,%9}, {%0,%1,%2,%3};"
        : "+f"(d[0]), "+f"(d[1]), "+f"(d[2]), "+f"(d[3])
        : "r"(a[0]), "r"(a[1]), "r"(a[2]), "r"(a[3]), "r"(b[0]), "r"(b[1]));
}

__device__ __forceinline__ void ldsm4(unsigned a[4], const half* p) {
    unsigned addr = (unsigned)__cvta_generic_to_shared(p);
    asm volatile("ldmatrix.sync.aligned.m8n8.x4.shared.b16 {%0,%1,%2,%3}, [%4];"
        : "=r"(a[0]), "=r"(a[1]), "=r"(a[2]), "=r"(a[3]) : "r"(addr));
}

#define ACC_ZERO2(acc) do { _Pragma("unroll") for (int _m=0;_m<2;_m++) _Pragma("unroll") for (int _n=0;_n<4;_n++) { acc[_m][_n][0]=0.f;acc[_m][_n][1]=0.f;acc[_m][_n][2]=0.f;acc[_m][_n][3]=0.f; } } while(0)

__device__ __forceinline__ void cpa16h(half* dst, const half* src) {
    unsigned u = (unsigned)__cvta_generic_to_shared(dst);
    asm volatile("cp.async.cg.shared.global [%0], [%1], 16;\n" :: "r"(u), "l"(src));
}
#define CP_COMMIT() asm volatile("cp.async.commit_group;\n")
#define CP_WAIT(n)  asm volatile("cp.async.wait_group %0;\n" :: "n"(n))

__device__ __forceinline__ void stageWh(half* dst, const half* __restrict__ W,
                                        int kc, int tid) {
#pragma unroll
    for (int j = 0; j < 2; j++) {
        int idx = (tid + j * NT) << 3;
        cpa16h(dst + idx, W + kc * WCHH + idx);
    }
}

// M=64 fp16 GEMM on fragment-packed weights, 3-stage W ring, ldmatrix A loads.
__device__ __forceinline__ void gemmH(float acc[2][4][4], const half* actH,
                                      const half* __restrict__ Wg,
                                      half* sWbuf, int tid) {
    const int lane = tid & 31, w = tid >> 5;
    const int mg = w & 1, ng = w >> 1;
    const int g = lane >> 2, t = lane & 3;
    const int arow = lane & 15, acol = (lane >> 4) << 3;
    stageWh(sWbuf, Wg, 0, tid);
    CP_COMMIT();
#pragma unroll
    for (int kc = 0; kc < 4; kc++) {
        if (kc < 3) {
            stageWh(sWbuf + ((kc + 1) % 3) * WCHH, Wg, kc + 1, tid);
            CP_COMMIT();
            CP_WAIT(1);
        } else {
            CP_WAIT(0);
        }
        __syncthreads();
        const half* sw = sWbuf + (kc % 3) * WCHH;
#pragma unroll
        for (int ks2 = 0; ks2 < 2; ks2++) {
            unsigned bb[4][2];
#pragma unroll
            for (int nt = 0; nt < 4; nt++) {
                int n = ng * 32 + nt * 8 + g;
                uint2 bv = *(const uint2*)(sw + ks2 * 2048 + n * 16 + t * 4);
                bb[nt][0] = bv.x; bb[nt][1] = bv.y;
            }
            const int k0 = kc * 32 + ks2 * 16;
#pragma unroll
            for (int mt = 0; mt < 2; mt++) {
                unsigned a4[4];
                ldsm4(a4, actH + ((mg * 2 + mt) * 16 + arow) * LDH + k0 + acol);
#pragma unroll
                for (int nt = 0; nt < 4; nt++) mma_f16(acc[mt][nt], a4, bb[nt]);
            }
        }
    }
    __syncthreads();
}

// store acc (half) into a 64xLDH smem tile, ALL 64 rows (pad rows come out 0)
__device__ __forceinline__ void storeHalfTile(half* dst, float acc[2][4][4], int tid) {
    const int lane = tid & 31, w = tid >> 5;
    const int mg = w & 1, ng = w >> 1;
    const int qr = lane >> 2, qc = lane & 3;
#pragma unroll
    for (int mt = 0; mt < 2; mt++)
#pragma unroll
        for (int hh = 0; hh < 2; hh++) {
            int r = (mg * 2 + mt) * 16 + qr + hh * 8;
#pragma unroll
            for (int nt = 0; nt < 4; nt++) {
                int c = ng * 32 + nt * 8 + qc * 2;
                *(half2*)(dst + r * LDH + c) =
                    __floats2half2_rn(acc[mt][nt][hh * 2], acc[mt][nt][hh * 2 + 1]);
            }
        }
}

// warp-parallel LN row stats over 64 rows of fp32 X (stride LDAX) -> scr[row], scr[64+row]
__device__ __forceinline__ void ln_stats(const float* X, float* scr, int tid) {
    const int lane = tid & 31, w = tid >> 5;
#pragma unroll
    for (int rr = 0; rr < 8; rr++) {
        int row = w * 8 + rr;
        float4 v = *(const float4*)(X + row * LDAX + lane * 4);
        float s  = v.x + v.y + v.z + v.w;
        float sq = v.x * v.x + v.y * v.y + v.z * v.z + v.w * v.w;
#pragma unroll
        for (int o = 16; o > 0; o >>= 1) {
            s  += __shfl_xor_sync(0xFFFFFFFFu, s, o);
            sq += __shfl_xor_sync(0xFFFFFFFFu, sq, o);
        }
        if (lane == 0) {
            float m = s * (1.0f / 128.0f);
            float var = sq * (1.0f / 128.0f) - m * m;
            scr[row] = m;
            scr[64 + row] = rsqrtf(var + 1e-5f);
        }
    }
}

// ------------------- kernel 0: pack weights to fp16 fragment order ----------
__global__ void k_prep(const float* __restrict__ e_w, const float* __restrict__ wq,
                       const float* __restrict__ wk, const float* __restrict__ wv,
                       const float* __restrict__ wq_src, const float* __restrict__ afc_w,
                       const float* __restrict__ f_w1, const float* __restrict__ f_w2)
{
    int i = blockIdx.x * 256 + threadIdx.x;
    if (i >= W_TOT) return;
    const float* src; int rel; int ldw = 128; int kbase = 0; int nbase = 0;
    if      (i < W_Q)   { src = e_w;    rel = i - W_EW; }
    else if (i < W_K)   { src = wq;     rel = i - W_Q; }
    else if (i < W_V)   { src = wk;     rel = i - W_K; }
    else if (i < W_QS)  { src = wv;     rel = i - W_V; }
    else if (i < W_AFC) { src = wq_src; rel = i - W_QS; }
    else if (i < W_F1)  { src = afc_w;  rel = i - W_AFC; }
    else if (i < W_F2)  { src = f_w1;   rel = i - W_F1;
                          int c = rel / 16384; rel -= c * 16384; ldw = 512; nbase = c * 128; }
    else                { src = f_w2;   rel = i - W_F2;
                          int c = rel / 16384; rel -= c * 16384; kbase = c * 128; }
    int kc = rel >> 12;
    int within = rel & 4095;
    int ks2 = within >> 11;
    int remn = within & 2047;
    int n = remn >> 4;
    int rem2 = remn & 15;
    int t = rem2 >> 2;
    int e = rem2 & 3;
    int k = kc * 32 + ks2 * 16 + 2 * t + (e & 1) + 8 * (e >> 1);
    g_wbuf[i] = __float2half_rn(src[(size_t)(kbase + k) * ldw + nbase + n]);
}

// ------------------- THE kernel: entire layer, 3 nodes per CTA --------------
__global__ __launch_bounds__(NT, 2)
void k_all(const float* __restrict__ nh, const float* __restrict__ t,
           const float* __restrict__ t_now, const float* __restrict__ ef,
           const float* __restrict__ bfreq, const float* __restrict__ phase,
           const float* __restrict__ e_b, const float* __restrict__ wq_src,
           const float* __restrict__ afc_b, const float* __restrict__ aln_g,
           const float* __restrict__ aln_b,
           const float* __restrict__ f_b1, const float* __restrict__ f_b2,
           const float* __restrict__ fln_g, const float* __restrict__ fln_b,
           const float* __restrict__ f2n_w, const float* __restrict__ f2n_b,
           const float* __restrict__ oln_g, const float* __restrict__ oln_b,
           float* __restrict__ out, int Ntot)
{
    extern __shared__ char smx[];
    half*  sZ  = (half*)smx;                 // z -> later FFN hidden H
    half*  sQ  = sZ + 64 * LDH;              // ef -> Q -> O -> x(half)
    half*  sK  = sQ + 64 * LDH;              // K ┐
    half*  sV  = sK + 64 * LDH;              // V ┘ after attention: X fp32 alias
    float* sX  = (float*)sK;                 // 64*LDAX fp32 (33792B <= 34816B)
    half*  sW  = sV + 64 * LDH;              // 3*WCHH
    float* scr = (float*)(sW + 3 * WCHH);    // 1088 floats
    const int tid = threadIdx.x;
    const int nb0 = blockIdx.x * 3;
    const int nodes_here = min(3, Ntot - nb0);
    const int rows = nodes_here * 20;
    const long grow0 = (long)nb0 * 20;
    const size_t gbase = (size_t)grow0 * 128;

    const int lane = tid & 31, w = tid >> 5;
    const int mg = w & 1, ng = w >> 1;
    const int qr = lane >> 2, qc = lane & 3;

    // ---- stage ef -> sQ (half), pad rows zero ----
#pragma unroll
    for (int j = 0; j < 8; j++) {
        int idx = tid + j * NT;
        int r = idx >> 5;
        int c4 = (idx & 31) << 2;
        float4 v = make_float4(0.f, 0.f, 0.f, 0.f);
        if (r < rows) v = *(const float4*)(ef + gbase + (size_t)r * 128 + c4);
        half2* dp = (half2*)(sQ + r * LDH + c4);
        dp[0] = __floats2half2_rn(v.x, v.y);
        dp[1] = __floats2half2_rn(v.z, v.w);
    }
    __syncthreads();

    float acc[2][4][4];

    // ---- z = nh + gelu(ef@We + be) + timeenc -> sZ (half) ----
    ACC_ZERO2(acc);
    gemmH(acc, sQ, g_wbuf + W_EW, sW, tid);
    const float tn = t_now[0];
#pragma unroll
    for (int mt = 0; mt < 2; mt++)
#pragma unroll
        for (int hh = 0; hh < 2; hh++) {
            int lr = (mg * 2 + mt) * 16 + qr + hh * 8;
            bool ok = (lr < rows);
            float tv = ok ? t[grow0 + lr] : 0.f;
#pragma unroll
            for (int nt = 0; nt < 4; nt++) {
                int cc = ng * 32 + nt * 8 + qc * 2;
                float zv0 = 0.f, zv1 = 0.f;
                if (ok) {
                    float g0 = gelu_exact(acc[mt][nt][hh * 2] + e_b[cc]);
                    float g1 = gelu_exact(acc[mt][nt][hh * 2 + 1] + e_b[cc + 1]);
                    zv0 = nh[gbase + (size_t)lr * 128 + cc] + g0 + cosf((tn - tv) * bfreq[cc] + phase[cc]);
                    zv1 = nh[gbase + (size_t)lr * 128 + cc + 1] + g1 + cosf((tn - tv) * bfreq[cc + 1] + phase[cc + 1]);
                }
                *(half2*)(sZ + lr * LDH + cc) = __floats2half2_rn(zv0, zv1);
            }
        }
    __syncthreads();

    // ---- Q, K, V GEMMs (A = sZ) ----
    ACC_ZERO2(acc); gemmH(acc, sZ, g_wbuf + W_Q, sW, tid); storeHalfTile(sQ, acc, tid);
    ACC_ZERO2(acc); gemmH(acc, sZ, g_wbuf + W_K, sW, tid); storeHalfTile(sK, acc, tid);
    ACC_ZERO2(acc); gemmH(acc, sZ, g_wbuf + W_V, sW, tid); storeHalfTile(sV, acc, tid);
    __syncthreads();   // V tile stores visible before self_q overwrites row 19

    // ---- self_q (scalar): z row19 @ wq_src -> rows 19 of Q,K,V ----
    for (int idx = tid; idx < nodes_here * 128; idx += NT) {
        int nn = idx >> 7, d = idx & 127;
        const half* z19 = sZ + (nn * 20 + 19) * LDH;
        float a = 0.f;
#pragma unroll 8
        for (int e = 0; e < 128; e++)
            a += __half2float(z19[e]) * wq_src[e * 128 + d];
        half hv = __float2half_rn(a);
        int r = nn * 20 + 19;
        sQ[r * LDH + d] = hv;
        sK[r * LDH + d] = hv;
        sV[r * LDH + d] = hv;
    }
    __syncthreads();

    // ---- attention: thread owns (node, h, qi); q from sQ ----
    const int anode = tid / 80, ah = (tid / 20) % 4, aqi = tid % 20;
    const bool active = tid < nodes_here * 80;
    float oacc[32];
    if (active) {
        float qf[32];
        const half* qp = sQ + (anode * 20 + aqi) * LDH + ah * 32;
#pragma unroll
        for (int j = 0; j < 16; j++) {
            float2 f = __half22float2(*(const half2*)(qp + 2 * j));
            qf[2 * j] = f.x; qf[2 * j + 1] = f.y;
        }
        float p[20];
#pragma unroll
        for (int ki = 0; ki < 20; ki++) {
            const half* kp = sK + (anode * 20 + ki) * LDH + ah * 32;
            float s = 0.f;
#pragma unroll
            for (int j = 0; j < 16; j++) {
                float2 kv = __half22float2(*(const half2*)(kp + 2 * j));
                s += qf[2 * j] * kv.x + qf[2 * j + 1] * kv.y;
            }
            p[ki] = s * 0.17677669529663687f;
        }
        float m = p[0];
#pragma unroll
        for (int ki = 1; ki < 20; ki++) m = fmaxf(m, p[ki]);
        float ssum = 0.f;
#pragma unroll
        for (int ki = 0; ki < 20; ki++) { p[ki] = expf(p[ki] - m); ssum += p[ki]; }
        float inv = 1.f / ssum;
#pragma unroll
        for (int j = 0; j < 32; j++) oacc[j] = 0.f;
#pragma unroll
        for (int ki = 0; ki < 20; ki++) {
            float pw = p[ki] * inv;
            const half* vp = sV + (anode * 20 + ki) * LDH + ah * 32;
#pragma unroll
            for (int j = 0; j < 16; j++) {
                float2 vv = __half22float2(*(const half2*)(vp + 2 * j));
                oacc[2 * j]     += pw * vv.x;
                oacc[2 * j + 1] += pw * vv.y;
            }
        }
    }
    __syncthreads();   // all Q/K/V reads done

    // O -> sQ (pad rows of sQ are 0 from Q GEMM)
    if (active) {
        half* op = sQ + (anode * 20 + aqi) * LDH + ah * 32;
#pragma unroll
        for (int j = 0; j < 16; j++)
            *(half2*)(op + 2 * j) = __floats2half2_rn(oacc[2 * j], oacc[2 * j + 1]);
    }
    // first sync inside next gemm orders these writes (and frees sK/sV alias after its reads)

    // ---- attn_fc GEMM -> X fp32 (alias over sK/sV) + bias + z residual ----
    ACC_ZERO2(acc);
    gemmH(acc, sQ, g_wbuf + W_AFC, sW, tid);
#pragma unroll
    for (int mt = 0; mt < 2; mt++)
#pragma unroll
        for (int hh = 0; hh < 2; hh++) {
            int r = (mg * 2 + mt) * 16 + qr + hh * 8;
#pragma unroll
            for (int nt = 0; nt < 4; nt++) {
                int c = ng * 32 + nt * 8 + qc * 2;
                float2 zv = __half22float2(*(const half2*)(sZ + r * LDH + c));
                sX[r * LDAX + c]     = acc[mt][nt][hh * 2]     + afc_b[c]     + zv.x;
                sX[r * LDAX + c + 1] = acc[mt][nt][hh * 2 + 1] + afc_b[c + 1] + zv.y;
            }
        }
    __syncthreads();

    // ---- attn LN (warp-parallel stats) -> x: half in sQ + fp32 in sX ----
    ln_stats(sX, scr, tid);
    __syncthreads();
    for (int i = tid; i < rows * 128; i += NT) {
        int r = i >> 7, d = i & 127;
        float y = (sX[r * LDAX + d] - scr[r]) * scr[64 + r] * aln_g[d] + aln_b[d];
        sQ[r * LDH + d] = __float2half_rn(y);
        sX[r * LDAX + d] = y;
    }
    for (int i = tid + rows * 128; i < 64 * 128; i += NT) {   // zero pad rows of x-half
        int r = i >> 7, d = i & 127;
        sQ[r * LDH + d] = __float2half_rn(0.f);
    }
    __syncthreads();

    // ---- FFN: 4 column chunks of 128; x2 accumulated in registers ----
    float x2[2][4][4];
    ACC_ZERO2(x2);
    for (int c = 0; c < 4; c++) {
        ACC_ZERO2(acc);
        gemmH(acc, sQ, g_wbuf + W_F1 + c * 16384, sW, tid);
#pragma unroll
        for (int mt = 0; mt < 2; mt++)
#pragma unroll
            for (int hh = 0; hh < 2; hh++) {
                int r = (mg * 2 + mt) * 16 + qr + hh * 8;
#pragma unroll
                for (int nt = 0; nt < 4; nt++) {
                    int col = ng * 32 + nt * 8 + qc * 2;
                    float b0 = f_b1[c * 128 + col], b1 = f_b1[c * 128 + col + 1];
                    *(half2*)(sZ + r * LDH + col) = __floats2half2_rn(
                        fmaxf(acc[mt][nt][hh * 2] + b0, 0.f),
                        fmaxf(acc[mt][nt][hh * 2 + 1] + b1, 0.f));
                }
            }
        __syncthreads();
        gemmH(x2, sZ, g_wbuf + W_F2 + c * 16384, sW, tid);
    }

    // y2 = x2 + b2 + x(post-LN fp32) -> sX in place
#pragma unroll
    for (int mt = 0; mt < 2; mt++)
#pragma unroll
        for (int hh = 0; hh < 2; hh++) {
            int r = (mg * 2 + mt) * 16 + qr + hh * 8;
#pragma unroll
            for (int nt = 0; nt < 4; nt++) {
                int col = ng * 32 + nt * 8 + qc * 2;
                sX[r * LDAX + col]     += x2[mt][nt][hh * 2]     + f_b2[col];
                sX[r * LDAX + col + 1] += x2[mt][nt][hh * 2 + 1] + f_b2[col + 1];
            }
        }
    __syncthreads();

    // ---- FFN LN (warp-parallel stats) -> sX fp32 in place ----
    ln_stats(sX, scr, tid);
    __syncthreads();
    for (int i = tid; i < rows * 128; i += NT) {
        int r = i >> 7, d = i & 127;
        sX[r * LDAX + d] = (sX[r * LDAX + d] - scr[r]) * scr[64 + r] * fln_g[d] + fln_b[d];
    }
    __syncthreads();

    // ---- fuse: neighborhood mean, fea2node, out LN ----
    float* sNe = scr + 128;   // 384
    float* sY  = scr + 512;   // 384
    for (int i = tid; i < nodes_here * 128; i += NT) {
        int nn = i >> 7, d = i & 127;
        float s = 0.f;
#pragma unroll
        for (int k = 0; k < 19; k++) s += sX[(nn * 20 + k) * LDAX + d];
        sNe[i] = s * (1.0f / 19.0f);
    }
    __syncthreads();
    for (int idx = tid; idx < nodes_here * 128; idx += NT) {
        int nn = idx >> 7, d = idx & 127;
        const float* selfr = sX + (nn * 20 + 19) * LDAX;
        const float* ne = sNe + nn * 128;
        float a = 0.f;
#pragma unroll 4
        for (int e = 0; e < 128; e++) a += selfr[e] * f2n_w[e * 128 + d];
#pragma unroll 4
        for (int e = 0; e < 128; e++) a += ne[e] * f2n_w[(128 + e) * 128 + d];
        float y = gelu_exact(a + f2n_b[d])
                + nh[gbase + (size_t)(nn * 20 + 19) * 128 + d];
        sY[idx] = y;
    }
    __syncthreads();
    if (w < nodes_here) {   // warp w handles node w: shuffle-reduce stats
        float4 v = *(const float4*)(sY + w * 128 + lane * 4);
        float s  = v.x + v.y + v.z + v.w;
        float sq = v.x * v.x + v.y * v.y + v.z * v.z + v.w * v.w;
#pragma unroll
        for (int o = 16; o > 0; o >>= 1) {
            s  += __shfl_xor_sync(0xFFFFFFFFu, s, o);
            sq += __shfl_xor_sync(0xFFFFFFFFu, sq, o);
        }
        if (lane == 0) {
            float m = s * (1.0f / 128.0f);
            float var = sq * (1.0f / 128.0f) - m * m;
            scr[1024 + w] = m;
            scr[1028 + w] = rsqrtf(var + 1e-5f);
        }
    }
    __syncthreads();
    for (int idx = tid; idx < nodes_here * 128; idx += NT) {
        int nn = idx >> 7, d = idx & 127;
        float y = (sY[idx] - scr[1024 + nn]) * scr[1028 + nn];
        out[(size_t)(nb0 + nn) * 128 + d] = y * oln_g[d] + oln_b[d];
    }
}

// ------------------- launch -------------------
#define SM_ALL ((4 * 64 * LDH + 3 * WCHH) * 2 + 1088 * 4)

extern "C" void kernel_launch(void* const* d_in, const int* in_sizes, int n_in,
                              void* d_out, int out_size) {
    (void)n_in; (void)out_size;
    const float* nh      = (const float*)d_in[0];
    const float* t       = (const float*)d_in[1];
    const float* t_now   = (const float*)d_in[2];
    const float* ef      = (const float*)d_in[3];
    const float* bfreq   = (const float*)d_in[4];
    const float* phase   = (const float*)d_in[5];
    const float* e_w     = (const float*)d_in[6];
    const float* e_b     = (const float*)d_in[7];
    const float* wq      = (const float*)d_in[8];
    const float* wk      = (const float*)d_in[9];
    const float* wv      = (const float*)d_in[10];
    const float* wq_src  = (const float*)d_in[11];
    const float* afc_w   = (const float*)d_in[12];
    const float* afc_b   = (const float*)d_in[13];
    const float* aln_g   = (const float*)d_in[14];
    const float* aln_b   = (const float*)d_in[15];
    const float* f_w1    = (const float*)d_in[16];
    const float* f_b1    = (const float*)d_in[17];
    const float* f_w2    = (const float*)d_in[18];
    const float* f_b2    = (const float*)d_in[19];
    const float* fln_g   = (const float*)d_in[20];
    const float* fln_b   = (const float*)d_in[21];
    const float* f2n_w   = (const float*)d_in[22];
    const float* f2n_b   = (const float*)d_in[23];
    const float* oln_g   = (const float*)d_in[24];
    const float* oln_b   = (const float*)d_in[25];
    float* out = (float*)d_out;

    const int N = in_sizes[0] / 2560;

    cudaFuncSetAttribute(k_all, cudaFuncAttributeMaxDynamicSharedMemorySize, SM_ALL);

    k_prep<<<(W_TOT + 255) / 256, 256>>>(e_w, wq, wk, wv, wq_src, afc_w, f_w1, f_w2);
    k_all<<<(N + 2) / 3, NT, SM_ALL>>>(nh, t, t_now, ef, bfreq, phase, e_b, wq_src,
                                       afc_b, aln_g, aln_b,
                                       f_b1, f_b2, fln_g, fln_b,
                                       f2n_w, f2n_b, oln_g, oln_b, out, N);
}